// round 10
// baseline (speedup 1.0000x reference)
#include <cuda_runtime.h>
#include <cuda_bf16.h>
#include <math.h>
#include <stdint.h>

#define Bq 4
#define Nq 1024
#define Cq 256
#define Hq 60
#define Wq 80
#define HWq (Hq*Wq)          // 4800
#define GS 8.0f
#define NUM_NEG 4
#define NSEC 10              // col sections of 512
#define MPAD (NSEC*512)      // 5120 padded cols
#define TILEB 18432          // 128 rows * 144B
#define SMEM_GEMM (6*TILEB)  // A0..A3 + B0,B1 = 110592 B

// ---------------- scratch (device globals; no allocs allowed) ----------------
__device__ float g_d2t[Bq*HWq*Cq];            // raw desc2 transposed [b][m][c]
__device__ __nv_bfloat16 g_kdb[Bq*Nq*Cq];     // normalized kp1 desc, bf16
__device__ __nv_bfloat16 g_d2b[Bq*MPAD*Cq];   // normalized desc2, bf16, padded
__device__ float g_pos[Bq*Nq];
__device__ int   g_nbr[Bq*Nq*16];             // 16 penalized cell ids per row
__device__ float g_part[Bq*Nq*NSEC*4];        // per-section partial top-4
__device__ float g_rowloss[Bq*Nq];

// ---------------- helpers ----------------
__device__ __forceinline__ void ins4(float* t, float v) {
    if (v < t[3]) {
        if (v < t[2]) {
            t[3] = t[2];
            if (v < t[1]) { t[2] = t[1]; if (v < t[0]) { t[1] = t[0]; t[0] = v; } else t[1] = v; }
            else t[2] = v;
        } else t[3] = v;
    }
}
__device__ __forceinline__ uint32_t s2u(const void* p) {
    uint32_t a;
    asm("{ .reg .u64 t; cvta.to.shared.u64 t, %1; cvt.u32.u64 %0, t; }" : "=r"(a) : "l"(p));
    return a;
}
__device__ __forceinline__ void cpa16(uint32_t dst, const void* src) {
    asm volatile("cp.async.cg.shared.global [%0], [%1], 16;" :: "r"(dst), "l"(src));
}
__device__ __forceinline__ void ldsm_x4(uint32_t* r, uint32_t addr) {
    asm volatile("ldmatrix.sync.aligned.m8n8.x4.shared.b16 {%0,%1,%2,%3}, [%4];"
                 : "=r"(r[0]), "=r"(r[1]), "=r"(r[2]), "=r"(r[3]) : "r"(addr));
}
__device__ __forceinline__ float wred_sum(float v) {
    #pragma unroll
    for (int o = 16; o > 0; o >>= 1) v += __shfl_xor_sync(0xffffffffu, v, o);
    return v;
}

// 4 nearest grid centers to (px,py): compares clip(aa+bb-2ab, 1e-12) — the
// sqrt of the reference is strictly monotone on this value, so ordering and
// tie-breaking (lower index first) are identical.  Nearest 4 centers always
// lie in a clamped 5x5 window around floor(p/8).
__device__ void top4cells(float px, float py, int* out) {
    int cx0 = (int)floorf(px * 0.125f);
    int cy0 = (int)floorf(py * 0.125f);
    int lx = min(max(cx0 - 2, 0), Wq - 5);
    int ly = min(max(cy0 - 2, 0), Hq - 5);
    float bd0 = 1e30f, bd1 = 1e30f, bd2 = 1e30f, bd3 = 1e30f;
    int   bi0 = -1, bi1 = -1, bi2 = -1, bi3 = -1;
    float aa = px*px + py*py;
    for (int yy = ly; yy < ly + 5; yy++) {
        float cy = (yy + 0.5f) * GS;
        for (int xx = lx; xx < lx + 5; xx++) {
            float cx = (xx + 0.5f) * GS;
            float bb = cx*cx + cy*cy;
            float ab = px*cx + py*cy;
            float d = fmaxf(aa + bb - 2.0f*ab, 1e-12f);
            int id = yy * Wq + xx;
            if (d < bd3) {
                if (d < bd2) {
                    bd3 = bd2; bi3 = bi2;
                    if (d < bd1) {
                        bd2 = bd1; bi2 = bi1;
                        if (d < bd0) { bd1 = bd0; bi1 = bi0; bd0 = d; bi0 = id; }
                        else         { bd1 = d; bi1 = id; }
                    } else { bd2 = d; bi2 = id; }
                } else { bd3 = d; bi3 = id; }
            }
        }
    }
    out[0] = bi0; out[1] = bi1; out[2] = bi2; out[3] = bi3;
}

// ---------------- K1: fused norms + transpose + bf16 normalize --------------
__global__ void k_prep(const float* __restrict__ desc2) {
    __shared__ float tile[256][33];
    __shared__ float part[8][33];
    __shared__ float sinv[32];
    int b = blockIdx.y;
    int m0 = blockIdx.x * 32;
    int tid = threadIdx.x;

    if (m0 >= HWq) {     // padding rows of g_d2b -> zeros
        for (int i = tid; i < 32*Cq/2; i += 256) {
            int r = i / (Cq/2), c2 = i % (Cq/2);
            *(uint32_t*)&g_d2b[((size_t)b*MPAD + m0 + r)*Cq + c2*2] = 0u;
        }
        return;
    }

    int tx = tid & 31, ty = tid >> 5;
    #pragma unroll 8
    for (int q = 0; q < 32; q++) {
        int c = q*8 + ty;
        tile[c][tx] = desc2[((size_t)b*Cq + c)*HWq + m0 + tx];
    }
    __syncthreads();
    float ss = 0.f;
    #pragma unroll
    for (int i = 0; i < 32; i++) { float v = tile[ty*32 + i][tx]; ss += v*v; }
    part[ty][tx] = ss;
    __syncthreads();
    if (tid < 32) {
        float tot = 0.f;
        #pragma unroll
        for (int j = 0; j < 8; j++) tot += part[j][tid];
        sinv[tid] = 1.0f / sqrtf(tot + 1e-8f);
    }
    __syncthreads();
    #pragma unroll 4
    for (int r = 0; r < 32; r++) {
        float v = tile[tid][r];
        g_d2t[((size_t)b*HWq + m0 + r)*Cq + tid] = v;
        g_d2b[((size_t)b*MPAD + m0 + r)*Cq + tid] = __float2bfloat16(v * sinv[r]);
    }
}

// ---------------- K0: warp-per-row kd normalize + bilinear pos --------------
__global__ void k_kd_pos(const float* __restrict__ kp1_desc,
                         const float* __restrict__ w_kp1) {
    int row = blockIdx.x * 8 + (threadIdx.x >> 5);   // 8 warps/block
    int lane = threadIdx.x & 31;
    int b = row / Nq;

    // 8 channels per lane
    float v[8];
    *(float4*)&v[0] = *(const float4*)&kp1_desc[(size_t)row*Cq + lane*8];
    *(float4*)&v[4] = *(const float4*)&kp1_desc[(size_t)row*Cq + lane*8 + 4];
    float ss = 0.f;
    #pragma unroll
    for (int i = 0; i < 8; i++) ss += v[i]*v[i];
    ss = wred_sum(ss);
    float invk = 1.0f / sqrtf(ss + 1e-8f);

    __nv_bfloat16 kb[8];
    #pragma unroll
    for (int i = 0; i < 8; i++) kb[i] = __float2bfloat16(v[i]*invk);
    *(uint4*)&g_kdb[(size_t)row*Cq + lane*8] = *(uint4*)kb;

    float x = w_kp1[row*2 + 0] * 0.125f - 0.5f;
    float y = w_kp1[row*2 + 1] * 0.125f - 0.5f;
    float fx = floorf(x), fy = floorf(y);
    float wx = x - fx, wy = y - fy;
    int x0 = min(max((int)fx, 0), Wq - 1);
    int x1 = min(x0 + 1, Wq - 1);
    int y0 = min(max((int)fy, 0), Hq - 1);
    int y1 = min(y0 + 1, Hq - 1);
    const float* D = g_d2t + (size_t)b*HWq*Cq;
    const float* p00 = &D[(size_t)(y0*Wq + x0)*Cq + lane*8];
    const float* p01 = &D[(size_t)(y0*Wq + x1)*Cq + lane*8];
    const float* p10 = &D[(size_t)(y1*Wq + x0)*Cq + lane*8];
    const float* p11 = &D[(size_t)(y1*Wq + x1)*Cq + lane*8];
    float ws = 0.f, vw = 0.f;
    #pragma unroll
    for (int h = 0; h < 2; h++) {
        float4 a00 = *(const float4*)(p00 + h*4);
        float4 a01 = *(const float4*)(p01 + h*4);
        float4 a10 = *(const float4*)(p10 + h*4);
        float4 a11 = *(const float4*)(p11 + h*4);
        float c00[4] = {a00.x, a00.y, a00.z, a00.w};
        float c01[4] = {a01.x, a01.y, a01.z, a01.w};
        float c10[4] = {a10.x, a10.y, a10.z, a10.w};
        float c11[4] = {a11.x, a11.y, a11.z, a11.w};
        #pragma unroll
        for (int i = 0; i < 4; i++) {
            float top = c00[i]*(1.f - wx) + c01[i]*wx;
            float bot = c10[i]*(1.f - wx) + c11[i]*wx;
            float wv = top*(1.f - wy) + bot*wy;
            ws += wv*wv;
            vw += v[h*4 + i]*wv;
        }
    }
    ws = wred_sum(ws);
    vw = wred_sum(vw);
    if (lane == 0) {
        float invw = 1.0f / sqrtf(ws + 1e-8f);
        g_pos[row] = 2.0f - 2.0f*(vw*invk*invw);
    }
}

// ---------------- K2: neighbourhood cell ids (one thread per (point, q)) ----
__global__ void k_nbr(const float* __restrict__ kp1,
                      const float* __restrict__ homo) {
    int idx = blockIdx.x * blockDim.x + threadIdx.x;
    if (idx >= Bq*Nq*4) return;
    int t = idx >> 2, q = idx & 3;
    int b = t / Nq;
    float px = kp1[t*2], py = kp1[t*2 + 1];
    const float* Hm = homo + b*9;
    int idx4[4];
    top4cells(px, py, idx4);
    int ci = idx4[q];
    int iy = ci / Wq, ix = ci % Wq;
    float cx = (ix + 0.5f)*GS, cy = (iy + 0.5f)*GS;
    float X = Hm[0]*cx + Hm[1]*cy + Hm[2];
    float Y = Hm[3]*cx + Hm[4]*cy + Hm[5];
    float Z = Hm[6]*cx + Hm[7]*cy + Hm[8];
    float wxp = X / (Z + 1e-8f);
    float wyp = Y / (Z + 1e-8f);
    top4cells(wxp, wyp, &g_nbr[(size_t)t*16 + q*4]);
}

// ---------------- K3: bf16 GEMM, 128 rows x 512 cols per CTA ----------------
// A (all K=256) resident in smem as 4 chunk-tiles [128][144B]; B streamed
// double-buffered over 16 (section,chunk) tiles.  Per-section top-4 folds
// into persistent registers; one block reduction at the end.
__global__ __launch_bounds__(256, 2) void k_gemm_bf16() {
    extern __shared__ char dsm[];
    __shared__ uint32_t mask[128][4];
    uint32_t sbase = s2u(dsm);

    int bm = blockIdx.x, bn = blockIdx.y, b = blockIdx.z;
    int tid = threadIdx.x;
    int lane = tid & 31, warp = tid >> 5;
    int wy = warp & 1, wx = warp >> 1;      // 2 x 4 warp grid
    int wrow = wy * 64, wcol = wx * 32;
    int g = lane >> 2, tig = lane & 3;
    int n0 = bn * 128, m0 = bm * 512;
    const __nv_bfloat16* A  = g_kdb + (size_t)b*Nq*Cq;
    const __nv_bfloat16* Bt = g_d2b + (size_t)b*MPAD*Cq;

    int crow = tid >> 3, c16 = tid & 7;     // B-tile copy mapping
    // prologue: A (all 4 chunks) + B tiles 0,1
    {
        int arow = tid >> 5, ac = tid & 31;       // 8 rows/pass, 32 x 16B cols
        #pragma unroll
        for (int h = 0; h < 16; h++) {
            int row = arow + h*8;
            uint32_t dst = sbase + (ac >> 3)*TILEB + row*144 + (ac & 7)*16;
            cpa16(dst, &A[(size_t)(n0 + row)*Cq + ac*8]);
        }
        #pragma unroll
        for (int h = 0; h < 4; h++) {
            int row = crow + h*32;
            cpa16(sbase + 4*TILEB + row*144 + c16*16, &Bt[(size_t)(m0 + row)*Cq + c16*8]);
        }
        asm volatile("cp.async.commit_group;" ::: "memory");   // G0 = A + B0
        #pragma unroll
        for (int h = 0; h < 4; h++) {
            int row = crow + h*32;
            cpa16(sbase + 5*TILEB + row*144 + c16*16,
                  &Bt[(size_t)(m0 + row)*Cq + 64 + c16*8]);    // tile1 = sec0,kc1
        }
        asm volatile("cp.async.commit_group;" ::: "memory");   // G1 = B1
    }

    float c[4][4][4];
    #pragma unroll
    for (int mt = 0; mt < 4; mt++)
        #pragma unroll
        for (int nt = 0; nt < 4; nt++)
            #pragma unroll
            for (int r = 0; r < 4; r++) c[mt][nt][r] = 0.f;

    float t4[8][4];
    #pragma unroll
    for (int r = 0; r < 8; r++)
        #pragma unroll
        for (int s = 0; s < 4; s++) t4[r][s] = 1e30f;

    for (int t = 0; t < 16; t++) {
        int sub = t >> 2, kc = t & 3, buf = t & 1;
        if (t < 15) asm volatile("cp.async.wait_group 1;" ::: "memory");
        else        asm volatile("cp.async.wait_group 0;" ::: "memory");
        __syncthreads();
        uint32_t aB = sbase + kc*TILEB;
        uint32_t bB = sbase + 4*TILEB + buf*TILEB;
        #pragma unroll
        for (int ks = 0; ks < 4; ks++) {
            int sk = ks * 16;
            uint32_t af[4][4], bf[4][2];
            #pragma unroll
            for (int mt = 0; mt < 4; mt++)
                ldsm_x4(af[mt], aB + (wrow + mt*16 + (lane & 15))*144
                                   + (sk + ((lane >> 4) << 3))*2);
            #pragma unroll
            for (int p = 0; p < 2; p++) {
                int mi = lane >> 3;
                int ntl = p*2 + (mi >> 1);
                int kh = mi & 1;
                uint32_t r[4];
                ldsm_x4(r, bB + (wcol + ntl*8 + (lane & 7))*144 + (sk + kh*8)*2);
                bf[p*2][0] = r[0]; bf[p*2][1] = r[1];
                bf[p*2+1][0] = r[2]; bf[p*2+1][1] = r[3];
            }
            #pragma unroll
            for (int mt = 0; mt < 4; mt++)
                #pragma unroll
                for (int nt = 0; nt < 4; nt++) {
                    asm volatile(
                        "mma.sync.aligned.m16n8k16.row.col.f32.bf16.bf16.f32 "
                        "{%0,%1,%2,%3}, {%4,%5,%6,%7}, {%8,%9}, {%0,%1,%2,%3};"
                        : "+f"(c[mt][nt][0]), "+f"(c[mt][nt][1]),
                          "+f"(c[mt][nt][2]), "+f"(c[mt][nt][3])
                        : "r"(af[mt][0]), "r"(af[mt][1]), "r"(af[mt][2]), "r"(af[mt][3]),
                          "r"(bf[nt][0]), "r"(bf[nt][1]));
                }
        }
        __syncthreads();
        if (t + 2 < 16) {    // refill consumed buffer with B tile t+2
            int t2 = t + 2;
            int msec = m0 + (t2 >> 2)*128;
            int koff = (t2 & 3)*64;
            uint32_t bT = sbase + 4*TILEB + buf*TILEB;
            #pragma unroll
            for (int h = 0; h < 4; h++) {
                int row = crow + h*32;
                cpa16(bT + row*144 + c16*16, &Bt[(size_t)(msec + row)*Cq + koff + c16*8]);
            }
            asm volatile("cp.async.commit_group;" ::: "memory");
        }
        if (kc == 3) {       // section done: build mask, fold top-4, reset
            int msec = m0 + sub*128;
            if (tid < 128) {
                uint32_t mk[4] = {0, 0, 0, 0};
                const int* nb = &g_nbr[(size_t)(b*Nq + n0 + tid)*16];
                #pragma unroll
                for (int q = 0; q < 16; q++) {
                    int loc = nb[q] - msec;
                    if (loc >= 0 && loc < 128) mk[loc >> 5] |= 1u << (loc & 31);
                }
                mask[tid][0] = mk[0]; mask[tid][1] = mk[1];
                mask[tid][2] = mk[2]; mask[tid][3] = mk[3];
            }
            __syncthreads();
            #pragma unroll
            for (int nt = 0; nt < 4; nt++) {
                int coll = wcol + nt*8 + tig*2;
                int colg = msec + coll;
                bool ok0 = colg < HWq, ok1 = (colg + 1) < HWq;
                #pragma unroll
                for (int mt = 0; mt < 4; mt++) {
                    int lr0 = wrow + mt*16 + g;
                    int lr1 = lr0 + 8;
                    float v00 = 2.f - 2.f*c[mt][nt][0];
                    float v01 = 2.f - 2.f*c[mt][nt][1];
                    float v10 = 2.f - 2.f*c[mt][nt][2];
                    float v11 = 2.f - 2.f*c[mt][nt][3];
                    uint32_t m0b0 = mask[lr0][coll >> 5], m0b1 = mask[lr0][(coll+1) >> 5];
                    uint32_t m1b0 = mask[lr1][coll >> 5], m1b1 = mask[lr1][(coll+1) >> 5];
                    if (ok0 && !((m0b0 >> (coll & 31)) & 1))     ins4(t4[mt*2],     v00);
                    if (ok1 && !((m0b1 >> ((coll+1) & 31)) & 1)) ins4(t4[mt*2],     v01);
                    if (ok0 && !((m1b0 >> (coll & 31)) & 1))     ins4(t4[mt*2 + 1], v10);
                    if (ok1 && !((m1b1 >> ((coll+1) & 31)) & 1)) ins4(t4[mt*2 + 1], v11);
                }
            }
            #pragma unroll
            for (int mt = 0; mt < 4; mt++)
                #pragma unroll
                for (int nt = 0; nt < 4; nt++)
                    #pragma unroll
                    for (int r = 0; r < 4; r++) c[mt][nt][r] = 0.f;
        }
    }

    // ---- block reduction in reused smem: 64 candidates -> top-4 per row ----
    float* red = (float*)dsm;   // [128][64], overlays dead A tiles
    __syncthreads();
    #pragma unroll
    for (int mt = 0; mt < 4; mt++) {
        int lr0 = wrow + mt*16 + g;
        int slot = (wx*4 + tig) * 4;
        *(float4*)&red[(lr0    )*64 + slot] = *(float4*)t4[mt*2];
        *(float4*)&red[(lr0 + 8)*64 + slot] = *(float4*)t4[mt*2 + 1];
    }
    __syncthreads();
    if (tid < 128) {
        float tt[4] = {1e30f, 1e30f, 1e30f, 1e30f};
        const float* r = &red[tid*64];
        #pragma unroll 8
        for (int q = 0; q < 64; q++) ins4(tt, r[q]);
        *(float4*)&g_part[((size_t)(b*Nq + n0 + tid)*NSEC + bm)*4] =
            make_float4(tt[0], tt[1], tt[2], tt[3]);
    }
}

// ---------------- K4: merge per-section partials, hinge ---------------------
__global__ void k_merge() {
    int row = blockIdx.x * 4 + (threadIdx.x >> 5);   // 4 warps/block
    int lane = threadIdx.x & 31;
    const float* p = &g_part[(size_t)row*NSEC*4];
    float t[4] = {1e30f, 1e30f, 1e30f, 1e30f};
    for (int i = lane; i < NSEC*4; i += 32) ins4(t, p[i]);
    #pragma unroll
    for (int off = 16; off > 0; off >>= 1) {
        float o0 = __shfl_xor_sync(0xffffffffu, t[0], off);
        float o1 = __shfl_xor_sync(0xffffffffu, t[1], off);
        float o2 = __shfl_xor_sync(0xffffffffu, t[2], off);
        float o3 = __shfl_xor_sync(0xffffffffu, t[3], off);
        float a[4] = {t[0], t[1], t[2], t[3]};
        float o[4] = {o0, o1, o2, o3};
        int ia = 0, ib = 0;
        #pragma unroll
        for (int k = 0; k < 4; k++) {
            float av = (ia < 4) ? a[ia] : 1e30f;
            float bv = (ib < 4) ? o[ib] : 1e30f;
            if (av <= bv) { t[k] = av; ia++; } else { t[k] = bv; ib++; }
        }
    }
    if (lane == 0) {
        float pos = g_pos[row];
        float lsum = 0.f;
        #pragma unroll
        for (int r = 0; r < 4; r++) lsum += fmaxf(pos - t[r] + 1.0f, 0.f);
        g_rowloss[row] = lsum;
    }
}

// ---------------- K5: deterministic final mean ------------------------------
__global__ void k_final(float* out) {
    __shared__ float red[256];
    int tid = threadIdx.x;
    float acc = 0.f;
    for (int i = tid; i < Bq*Nq; i += 256) acc += g_rowloss[i];
    red[tid] = acc; __syncthreads();
    for (int s = 128; s > 0; s >>= 1) {
        if (tid < s) red[tid] += red[tid + s];
        __syncthreads();
    }
    if (tid == 0) out[0] = red[0] / (float)(Bq*Nq*NUM_NEG);
}

// ---------------- launch ----------------------------------------------------
extern "C" void kernel_launch(void* const* d_in, const int* in_sizes, int n_in,
                              void* d_out, int out_size) {
    const float* kp1      = (const float*)d_in[0];
    const float* w_kp1    = (const float*)d_in[1];
    const float* kp1_desc = (const float*)d_in[2];
    const float* desc2    = (const float*)d_in[3];
    const float* homo     = (const float*)d_in[4];
    float* out = (float*)d_out;

    cudaFuncSetAttribute(k_gemm_bf16, cudaFuncAttributeMaxDynamicSharedMemorySize, SMEM_GEMM);

    k_prep<<<dim3(MPAD/32, Bq), 256>>>(desc2);
    k_kd_pos<<<Bq*Nq/8, 256>>>(kp1_desc, w_kp1);
    k_nbr<<<(Bq*Nq*4)/64, 64>>>(kp1, homo);
    k_gemm_bf16<<<dim3(NSEC, Nq/128, Bq), 256, SMEM_GEMM>>>();
    k_merge<<<Bq*Nq/4, 128>>>();
    k_final<<<1, 256>>>(out);
}

// round 11
// speedup vs baseline: 1.2077x; 1.2077x over previous
#include <cuda_runtime.h>
#include <cuda_bf16.h>
#include <math.h>
#include <stdint.h>

#define Bq 4
#define Nq 1024
#define Cq 256
#define Hq 60
#define Wq 80
#define HWq (Hq*Wq)          // 4800
#define GS 8.0f
#define NUM_NEG 4
#define NSPLIT 38            // ceil(4800/128) col splits
#define MPAD (NSPLIT*128)    // 4864 padded cols
#define TILEB 18432          // 128 rows * 144B
#define SMEM_GEMM (4*TILEB)  // A0,B0,A1,B1 = 73728 B

// ---------------- scratch (device globals; no allocs allowed) ----------------
__device__ float g_d2t[Bq*HWq*Cq];            // raw desc2 transposed [b][m][c]
__device__ __nv_bfloat16 g_kdb[Bq*Nq*Cq];     // normalized kp1 desc, bf16
__device__ __nv_bfloat16 g_d2b[Bq*MPAD*Cq];   // normalized desc2, bf16, padded
__device__ float g_pos[Bq*Nq];
__device__ int   g_nbr[Bq*Nq*16];             // 16 penalized cell ids per row
__device__ float g_part[Bq*Nq*NSPLIT*4];      // per-split partial top-4
__device__ float g_rowloss[Bq*Nq];

// ---------------- helpers ----------------
__device__ __forceinline__ void ins4(float* t, float v) {
    if (v < t[3]) {
        if (v < t[2]) {
            t[3] = t[2];
            if (v < t[1]) { t[2] = t[1]; if (v < t[0]) { t[1] = t[0]; t[0] = v; } else t[1] = v; }
            else t[2] = v;
        } else t[3] = v;
    }
}
__device__ __forceinline__ uint32_t s2u(const void* p) {
    uint32_t a;
    asm("{ .reg .u64 t; cvta.to.shared.u64 t, %1; cvt.u32.u64 %0, t; }" : "=r"(a) : "l"(p));
    return a;
}
__device__ __forceinline__ void cpa16(uint32_t dst, const void* src) {
    asm volatile("cp.async.cg.shared.global [%0], [%1], 16;" :: "r"(dst), "l"(src));
}
__device__ __forceinline__ void ldsm_x4(uint32_t* r, uint32_t addr) {
    asm volatile("ldmatrix.sync.aligned.m8n8.x4.shared.b16 {%0,%1,%2,%3}, [%4];"
                 : "=r"(r[0]), "=r"(r[1]), "=r"(r[2]), "=r"(r[3]) : "r"(addr));
}
__device__ __forceinline__ float wred_sum(float v) {
    #pragma unroll
    for (int o = 16; o > 0; o >>= 1) v += __shfl_xor_sync(0xffffffffu, v, o);
    return v;
}

// 4 nearest grid centers to (px,py): compares clip(aa+bb-2ab, 1e-12) — the
// reference's sqrt is strictly monotone on this value, so ordering and
// tie-breaking (lower index first) are identical.  Nearest 4 centers always
// lie in a clamped 5x5 window around floor(p/8).
__device__ void top4cells(float px, float py, int* out) {
    int cx0 = (int)floorf(px * 0.125f);
    int cy0 = (int)floorf(py * 0.125f);
    int lx = min(max(cx0 - 2, 0), Wq - 5);
    int ly = min(max(cy0 - 2, 0), Hq - 5);
    float bd0 = 1e30f, bd1 = 1e30f, bd2 = 1e30f, bd3 = 1e30f;
    int   bi0 = -1, bi1 = -1, bi2 = -1, bi3 = -1;
    float aa = px*px + py*py;
    for (int yy = ly; yy < ly + 5; yy++) {
        float cy = (yy + 0.5f) * GS;
        for (int xx = lx; xx < lx + 5; xx++) {
            float cx = (xx + 0.5f) * GS;
            float bb = cx*cx + cy*cy;
            float ab = px*cx + py*cy;
            float d = fmaxf(aa + bb - 2.0f*ab, 1e-12f);
            int id = yy * Wq + xx;
            if (d < bd3) {
                if (d < bd2) {
                    bd3 = bd2; bi3 = bi2;
                    if (d < bd1) {
                        bd2 = bd1; bi2 = bi1;
                        if (d < bd0) { bd1 = bd0; bi1 = bi0; bd0 = d; bi0 = id; }
                        else         { bd1 = d; bi1 = id; }
                    } else { bd2 = d; bi2 = id; }
                } else { bd3 = d; bi3 = id; }
            }
        }
    }
    out[0] = bi0; out[1] = bi1; out[2] = bi2; out[3] = bi3;
}

// ---------------- K1: fused norms + transpose + bf16 normalize --------------
__global__ void k_prep(const float* __restrict__ desc2) {
    __shared__ float tile[256][33];
    __shared__ float part[8][33];
    __shared__ float sinv[32];
    int b = blockIdx.y;
    int m0 = blockIdx.x * 32;
    int tid = threadIdx.x;

    if (m0 >= HWq) {     // padding rows of g_d2b -> zeros
        for (int i = tid; i < 32*Cq/2; i += 256) {
            int r = i / (Cq/2), c2 = i % (Cq/2);
            *(uint32_t*)&g_d2b[((size_t)b*MPAD + m0 + r)*Cq + c2*2] = 0u;
        }
        return;
    }

    int tx = tid & 31, ty = tid >> 5;
    #pragma unroll 8
    for (int q = 0; q < 32; q++) {
        int c = q*8 + ty;
        tile[c][tx] = desc2[((size_t)b*Cq + c)*HWq + m0 + tx];
    }
    __syncthreads();
    float ss = 0.f;
    #pragma unroll
    for (int i = 0; i < 32; i++) { float v = tile[ty*32 + i][tx]; ss += v*v; }
    part[ty][tx] = ss;
    __syncthreads();
    if (tid < 32) {
        float tot = 0.f;
        #pragma unroll
        for (int j = 0; j < 8; j++) tot += part[j][tid];
        sinv[tid] = 1.0f / sqrtf(tot + 1e-8f);
    }
    __syncthreads();
    #pragma unroll 4
    for (int r = 0; r < 32; r++) {
        float v = tile[tid][r];
        g_d2t[((size_t)b*HWq + m0 + r)*Cq + tid] = v;
        g_d2b[((size_t)b*MPAD + m0 + r)*Cq + tid] = __float2bfloat16(v * sinv[r]);
    }
}

// ---------------- K0: warp-per-row kd normalize + bilinear pos + nbr --------
__global__ void k_kd_pos(const float* __restrict__ kp1_desc,
                         const float* __restrict__ w_kp1,
                         const float* __restrict__ kp1,
                         const float* __restrict__ homo) {
    int row = blockIdx.x * 8 + (threadIdx.x >> 5);   // 8 warps/block
    int lane = threadIdx.x & 31;
    int b = row / Nq;

    // 8 channels per lane
    float v[8];
    *(float4*)&v[0] = *(const float4*)&kp1_desc[(size_t)row*Cq + lane*8];
    *(float4*)&v[4] = *(const float4*)&kp1_desc[(size_t)row*Cq + lane*8 + 4];
    float ss = 0.f;
    #pragma unroll
    for (int i = 0; i < 8; i++) ss += v[i]*v[i];
    ss = wred_sum(ss);
    float invk = 1.0f / sqrtf(ss + 1e-8f);

    __nv_bfloat16 kb[8];
    #pragma unroll
    for (int i = 0; i < 8; i++) kb[i] = __float2bfloat16(v[i]*invk);
    *(uint4*)&g_kdb[(size_t)row*Cq + lane*8] = *(uint4*)kb;

    float x = w_kp1[row*2 + 0] * 0.125f - 0.5f;
    float y = w_kp1[row*2 + 1] * 0.125f - 0.5f;
    float fx = floorf(x), fy = floorf(y);
    float wx = x - fx, wy = y - fy;
    int x0 = min(max((int)fx, 0), Wq - 1);
    int x1 = min(x0 + 1, Wq - 1);
    int y0 = min(max((int)fy, 0), Hq - 1);
    int y1 = min(y0 + 1, Hq - 1);
    const float* D = g_d2t + (size_t)b*HWq*Cq;
    const float* p00 = &D[(size_t)(y0*Wq + x0)*Cq + lane*8];
    const float* p01 = &D[(size_t)(y0*Wq + x1)*Cq + lane*8];
    const float* p10 = &D[(size_t)(y1*Wq + x0)*Cq + lane*8];
    const float* p11 = &D[(size_t)(y1*Wq + x1)*Cq + lane*8];
    float ws = 0.f, vw = 0.f;
    #pragma unroll
    for (int h = 0; h < 2; h++) {
        float4 a00 = *(const float4*)(p00 + h*4);
        float4 a01 = *(const float4*)(p01 + h*4);
        float4 a10 = *(const float4*)(p10 + h*4);
        float4 a11 = *(const float4*)(p11 + h*4);
        float c00[4] = {a00.x, a00.y, a00.z, a00.w};
        float c01[4] = {a01.x, a01.y, a01.z, a01.w};
        float c10[4] = {a10.x, a10.y, a10.z, a10.w};
        float c11[4] = {a11.x, a11.y, a11.z, a11.w};
        #pragma unroll
        for (int i = 0; i < 4; i++) {
            float top = c00[i]*(1.f - wx) + c01[i]*wx;
            float bot = c10[i]*(1.f - wx) + c11[i]*wx;
            float wv = top*(1.f - wy) + bot*wy;
            ws += wv*wv;
            vw += v[h*4 + i]*wv;
        }
    }
    ws = wred_sum(ws);
    vw = wred_sum(vw);
    if (lane == 0) {
        float invw = 1.0f / sqrtf(ws + 1e-8f);
        g_pos[row] = 2.0f - 2.0f*(vw*invk*invw);
    }

    // fused neighbourhood ids: lanes 0-3 each handle one q
    if (lane < 4) {
        float px = kp1[row*2], py = kp1[row*2 + 1];
        const float* Hm = homo + b*9;
        int idx4[4];
        top4cells(px, py, idx4);
        int ci = idx4[lane];
        int iy = ci / Wq, ix = ci % Wq;
        float cx = (ix + 0.5f)*GS, cy = (iy + 0.5f)*GS;
        float X = Hm[0]*cx + Hm[1]*cy + Hm[2];
        float Y = Hm[3]*cx + Hm[4]*cy + Hm[5];
        float Z = Hm[6]*cx + Hm[7]*cy + Hm[8];
        float wxp = X / (Z + 1e-8f);
        float wyp = Y / (Z + 1e-8f);
        top4cells(wxp, wyp, &g_nbr[(size_t)row*16 + lane*4]);
    }
}

// ---------------- K3: bf16 m16n8k16 GEMM, cp.async 2-stage, ldmatrix --------
// Block 128 rows x 128 cols, 8 warps (2x4), warp tile 64x32.
// Dynamic smem: A0,B0,A1,B1 tiles of 128 rows x 144B.  Fused top-4 epilogue.
__global__ __launch_bounds__(256, 2) void k_gemm_bf16() {
    extern __shared__ char dsm[];
    __shared__ uint32_t mask[128][4];
    uint32_t sbase = s2u(dsm);

    int bm = blockIdx.x, bn = blockIdx.y, b = blockIdx.z;
    int tid = threadIdx.x;
    int lane = tid & 31, warp = tid >> 5;
    int wy = warp & 1, wx = warp >> 1;      // 2 x 4 warp grid
    int wrow = wy * 64, wcol = wx * 32;
    int g = lane >> 2, tig = lane & 3;
    int n0 = bn * 128, m0 = bm * 128;
    const __nv_bfloat16* A  = g_kdb + (size_t)b*Nq*Cq;
    const __nv_bfloat16* Bt = g_d2b + (size_t)b*MPAD*Cq;

    int crow = tid >> 3, c16 = tid & 7;     // copy mapping (x4 rows per h)
    // prefetch both buffers up-front
    #pragma unroll
    for (int kc = 0; kc < 2; kc++) {
        uint32_t aT = sbase + kc*2*TILEB;
        uint32_t bT = aT + TILEB;
        #pragma unroll
        for (int h = 0; h < 4; h++) {
            int row = crow + h*32;
            cpa16(aT + row*144 + c16*16, &A [(size_t)(n0 + row)*Cq + kc*64 + c16*8]);
            cpa16(bT + row*144 + c16*16, &Bt[(size_t)(m0 + row)*Cq + kc*64 + c16*8]);
        }
        asm volatile("cp.async.commit_group;" ::: "memory");
    }

    // penalty bitmask for this block's 128 rows x 128 local cols
    if (tid < 128) { mask[tid][0] = 0; mask[tid][1] = 0; mask[tid][2] = 0; mask[tid][3] = 0; }
    __syncthreads();
    {
        int row = tid >> 1;
        int qb  = (tid & 1) * 8;
        const int* nb = &g_nbr[(size_t)(b*Nq + n0 + row)*16];
        #pragma unroll
        for (int q = 0; q < 8; q++) {
            int loc = nb[qb + q] - m0;
            if (loc >= 0 && loc < 128)
                atomicOr(&mask[row][loc >> 5], 1u << (loc & 31));
        }
    }

    float c[4][4][4];
    #pragma unroll
    for (int mt = 0; mt < 4; mt++)
        #pragma unroll
        for (int nt = 0; nt < 4; nt++)
            #pragma unroll
            for (int r = 0; r < 4; r++) c[mt][nt][r] = 0.f;

    for (int kc = 0; kc < 4; kc++) {
        if (kc < 3) asm volatile("cp.async.wait_group 1;" ::: "memory");
        else        asm volatile("cp.async.wait_group 0;" ::: "memory");
        __syncthreads();
        int buf = kc & 1;
        uint32_t aB = sbase + buf*2*TILEB;
        uint32_t bB = aB + TILEB;
        #pragma unroll
        for (int ks = 0; ks < 4; ks++) {
            int sk = ks * 16;
            uint32_t af[4][4], bf[4][2];
            #pragma unroll
            for (int mt = 0; mt < 4; mt++)
                ldsm_x4(af[mt], aB + (wrow + mt*16 + (lane & 15))*144
                                   + (sk + ((lane >> 4) << 3))*2);
            #pragma unroll
            for (int p = 0; p < 2; p++) {
                int mi = lane >> 3;
                int ntl = p*2 + (mi >> 1);
                int kh = mi & 1;
                uint32_t r[4];
                ldsm_x4(r, bB + (wcol + ntl*8 + (lane & 7))*144 + (sk + kh*8)*2);
                bf[p*2][0] = r[0]; bf[p*2][1] = r[1];
                bf[p*2+1][0] = r[2]; bf[p*2+1][1] = r[3];
            }
            #pragma unroll
            for (int mt = 0; mt < 4; mt++)
                #pragma unroll
                for (int nt = 0; nt < 4; nt++) {
                    asm volatile(
                        "mma.sync.aligned.m16n8k16.row.col.f32.bf16.bf16.f32 "
                        "{%0,%1,%2,%3}, {%4,%5,%6,%7}, {%8,%9}, {%0,%1,%2,%3};"
                        : "+f"(c[mt][nt][0]), "+f"(c[mt][nt][1]),
                          "+f"(c[mt][nt][2]), "+f"(c[mt][nt][3])
                        : "r"(af[mt][0]), "r"(af[mt][1]), "r"(af[mt][2]), "r"(af[mt][3]),
                          "r"(bf[nt][0]), "r"(bf[nt][1]));
                }
        }
        __syncthreads();
        if (kc + 2 < 4) {   // refill the buffer just consumed
            uint32_t aT = sbase + buf*2*TILEB;
            uint32_t bT = aT + TILEB;
            #pragma unroll
            for (int h = 0; h < 4; h++) {
                int row = crow + h*32;
                cpa16(aT + row*144 + c16*16, &A [(size_t)(n0 + row)*Cq + (kc+2)*64 + c16*8]);
                cpa16(bT + row*144 + c16*16, &Bt[(size_t)(m0 + row)*Cq + (kc+2)*64 + c16*8]);
            }
            asm volatile("cp.async.commit_group;" ::: "memory");
        }
    }

    // ---- epilogue: per-thread running top-4 per row (sim = 2 - 2*acc) ----
    float t4[8][4];
    #pragma unroll
    for (int r = 0; r < 8; r++)
        #pragma unroll
        for (int s = 0; s < 4; s++) t4[r][s] = 1e30f;

    #pragma unroll
    for (int nt = 0; nt < 4; nt++) {
        int coll = wcol + nt*8 + tig*2;       // local col (even)
        int colg = m0 + coll;
        bool ok0 = colg < HWq, ok1 = (colg + 1) < HWq;
        #pragma unroll
        for (int mt = 0; mt < 4; mt++) {
            int lr0 = wrow + mt*16 + g;
            int lr1 = lr0 + 8;
            float v00 = 2.f - 2.f*c[mt][nt][0];
            float v01 = 2.f - 2.f*c[mt][nt][1];
            float v10 = 2.f - 2.f*c[mt][nt][2];
            float v11 = 2.f - 2.f*c[mt][nt][3];
            uint32_t m0b0 = mask[lr0][coll >> 5], m0b1 = mask[lr0][(coll+1) >> 5];
            uint32_t m1b0 = mask[lr1][coll >> 5], m1b1 = mask[lr1][(coll+1) >> 5];
            if (ok0 && !((m0b0 >> (coll & 31)) & 1))       ins4(t4[mt*2],     v00);
            if (ok1 && !((m0b1 >> ((coll+1) & 31)) & 1))   ins4(t4[mt*2],     v01);
            if (ok0 && !((m1b0 >> (coll & 31)) & 1))       ins4(t4[mt*2 + 1], v10);
            if (ok1 && !((m1b1 >> ((coll+1) & 31)) & 1))   ins4(t4[mt*2 + 1], v11);
        }
    }

    // ---- block reduction in reused dynamic smem: 64 cands -> top-4 per row --
    float* red = (float*)dsm;   // [128][64]
    __syncthreads();
    #pragma unroll
    for (int mt = 0; mt < 4; mt++) {
        int lr0 = wrow + mt*16 + g;
        int slot = (wx*4 + tig) * 4;
        *(float4*)&red[(lr0    )*64 + slot] = *(float4*)t4[mt*2];
        *(float4*)&red[(lr0 + 8)*64 + slot] = *(float4*)t4[mt*2 + 1];
    }
    __syncthreads();
    if (tid < 128) {
        float tt[4] = {1e30f, 1e30f, 1e30f, 1e30f};
        const float* r = &red[tid*64];
        #pragma unroll 8
        for (int q = 0; q < 64; q++) ins4(tt, r[q]);
        *(float4*)&g_part[((size_t)(b*Nq + n0 + tid)*NSPLIT + bm)*4] =
            make_float4(tt[0], tt[1], tt[2], tt[3]);
    }
}

// ---------------- K4: merge per-split partials, hinge ----------------------
__global__ void k_merge() {
    int row = blockIdx.x * 4 + (threadIdx.x >> 5);   // 4 warps/block
    int lane = threadIdx.x & 31;
    const float* p = &g_part[(size_t)row*NSPLIT*4];
    float t[4] = {1e30f, 1e30f, 1e30f, 1e30f};
    for (int i = lane; i < NSPLIT*4; i += 32) ins4(t, p[i]);
    #pragma unroll
    for (int off = 16; off > 0; off >>= 1) {
        float o0 = __shfl_xor_sync(0xffffffffu, t[0], off);
        float o1 = __shfl_xor_sync(0xffffffffu, t[1], off);
        float o2 = __shfl_xor_sync(0xffffffffu, t[2], off);
        float o3 = __shfl_xor_sync(0xffffffffu, t[3], off);
        float a[4] = {t[0], t[1], t[2], t[3]};
        float o[4] = {o0, o1, o2, o3};
        int ia = 0, ib = 0;
        #pragma unroll
        for (int k = 0; k < 4; k++) {
            float av = (ia < 4) ? a[ia] : 1e30f;
            float bv = (ib < 4) ? o[ib] : 1e30f;
            if (av <= bv) { t[k] = av; ia++; } else { t[k] = bv; ib++; }
        }
    }
    if (lane == 0) {
        float pos = g_pos[row];
        float lsum = 0.f;
        #pragma unroll
        for (int r = 0; r < 4; r++) lsum += fmaxf(pos - t[r] + 1.0f, 0.f);
        g_rowloss[row] = lsum;
    }
}

// ---------------- K5: deterministic final mean ------------------------------
__global__ void k_final(float* out) {
    __shared__ float red[256];
    int tid = threadIdx.x;
    float acc = 0.f;
    for (int i = tid; i < Bq*Nq; i += 256) acc += g_rowloss[i];
    red[tid] = acc; __syncthreads();
    for (int s = 128; s > 0; s >>= 1) {
        if (tid < s) red[tid] += red[tid + s];
        __syncthreads();
    }
    if (tid == 0) out[0] = red[0] / (float)(Bq*Nq*NUM_NEG);
}

// ---------------- launch ----------------------------------------------------
extern "C" void kernel_launch(void* const* d_in, const int* in_sizes, int n_in,
                              void* d_out, int out_size) {
    const float* kp1      = (const float*)d_in[0];
    const float* w_kp1    = (const float*)d_in[1];
    const float* kp1_desc = (const float*)d_in[2];
    const float* desc2    = (const float*)d_in[3];
    const float* homo     = (const float*)d_in[4];
    float* out = (float*)d_out;

    cudaFuncSetAttribute(k_gemm_bf16, cudaFuncAttributeMaxDynamicSharedMemorySize, SMEM_GEMM);

    k_prep<<<dim3(MPAD/32, Bq), 256>>>(desc2);
    k_kd_pos<<<Bq*Nq/8, 256>>>(kp1_desc, w_kp1, kp1, homo);
    k_gemm_bf16<<<dim3(NSPLIT, Nq/128, Bq), 256, SMEM_GEMM>>>();
    k_merge<<<Bq*Nq/4, 128>>>();
    k_final<<<1, 256>>>(out);
}

// round 12
// speedup vs baseline: 1.2261x; 1.0152x over previous
#include <cuda_runtime.h>
#include <cuda_bf16.h>
#include <math.h>
#include <stdint.h>

#define Bq 4
#define Nq 1024
#define Cq 256
#define Hq 60
#define Wq 80
#define HWq (Hq*Wq)          // 4800
#define GS 8.0f
#define NUM_NEG 4
#define NSPLIT 38            // ceil(4800/128) col splits
#define MPAD (NSPLIT*128)    // 4864 padded cols
#define TILEB 18432          // 128 rows * 144B
#define SMEM_GEMM (4*TILEB)  // A0,B0,A1,B1 = 73728 B

// ---------------- scratch (device globals; no allocs allowed) ----------------
__device__ float g_d2t[Bq*HWq*Cq];            // raw desc2 transposed [b][m][c]
__device__ __nv_bfloat16 g_kdb[Bq*Nq*Cq];     // normalized kp1 desc, bf16
__device__ __nv_bfloat16 g_d2b[Bq*MPAD*Cq];   // normalized desc2, bf16, padded
__device__ float g_pos[Bq*Nq];
__device__ int   g_nbr[Bq*Nq*16];             // 16 penalized cell ids per row
__device__ float g_part[Bq*Nq*NSPLIT*4];      // per-split partial top-4
__device__ float g_rowloss[Bq*Nq];

// ---------------- helpers ----------------
__device__ __forceinline__ void ins4(float* t, float v) {
    if (v < t[3]) {
        if (v < t[2]) {
            t[3] = t[2];
            if (v < t[1]) { t[2] = t[1]; if (v < t[0]) { t[1] = t[0]; t[0] = v; } else t[1] = v; }
            else t[2] = v;
        } else t[3] = v;
    }
}
__device__ __forceinline__ uint32_t s2u(const void* p) {
    uint32_t a;
    asm("{ .reg .u64 t; cvta.to.shared.u64 t, %1; cvt.u32.u64 %0, t; }" : "=r"(a) : "l"(p));
    return a;
}
__device__ __forceinline__ void cpa16(uint32_t dst, const void* src) {
    asm volatile("cp.async.cg.shared.global [%0], [%1], 16;" :: "r"(dst), "l"(src));
}
__device__ __forceinline__ void ldsm_x4(uint32_t* r, uint32_t addr) {
    asm volatile("ldmatrix.sync.aligned.m8n8.x4.shared.b16 {%0,%1,%2,%3}, [%4];"
                 : "=r"(r[0]), "=r"(r[1]), "=r"(r[2]), "=r"(r[3]) : "r"(addr));
}
__device__ __forceinline__ float wred_sum(float v) {
    #pragma unroll
    for (int o = 16; o > 0; o >>= 1) v += __shfl_xor_sync(0xffffffffu, v, o);
    return v;
}

// 4 nearest grid centers to (px,py): compares clip(aa+bb-2ab, 1e-12) — the
// reference's sqrt is strictly monotone on this value, so ordering and
// tie-breaking (lower index first) are identical.  Nearest 4 centers always
// lie in a clamped 5x5 window around floor(p/8).
__device__ void top4cells(float px, float py, int* out) {
    int cx0 = (int)floorf(px * 0.125f);
    int cy0 = (int)floorf(py * 0.125f);
    int lx = min(max(cx0 - 2, 0), Wq - 5);
    int ly = min(max(cy0 - 2, 0), Hq - 5);
    float bd0 = 1e30f, bd1 = 1e30f, bd2 = 1e30f, bd3 = 1e30f;
    int   bi0 = -1, bi1 = -1, bi2 = -1, bi3 = -1;
    float aa = px*px + py*py;
    for (int yy = ly; yy < ly + 5; yy++) {
        float cy = (yy + 0.5f) * GS;
        for (int xx = lx; xx < lx + 5; xx++) {
            float cx = (xx + 0.5f) * GS;
            float bb = cx*cx + cy*cy;
            float ab = px*cx + py*cy;
            float d = fmaxf(aa + bb - 2.0f*ab, 1e-12f);
            int id = yy * Wq + xx;
            if (d < bd3) {
                if (d < bd2) {
                    bd3 = bd2; bi3 = bi2;
                    if (d < bd1) {
                        bd2 = bd1; bi2 = bi1;
                        if (d < bd0) { bd1 = bd0; bi1 = bi0; bd0 = d; bi0 = id; }
                        else         { bd1 = d; bi1 = id; }
                    } else { bd2 = d; bi2 = id; }
                } else { bd3 = d; bi3 = id; }
            }
        }
    }
    out[0] = bi0; out[1] = bi1; out[2] = bi2; out[3] = bi3;
}

// ---------------- K1: fused norms + transpose + bf16 normalize --------------
__global__ void k_prep(const float* __restrict__ desc2) {
    __shared__ float tile[256][33];
    __shared__ float part[8][33];
    __shared__ float sinv[32];
    int b = blockIdx.y;
    int m0 = blockIdx.x * 32;
    int tid = threadIdx.x;

    if (m0 >= HWq) {     // padding rows of g_d2b -> zeros
        for (int i = tid; i < 32*Cq/2; i += 256) {
            int r = i / (Cq/2), c2 = i % (Cq/2);
            *(uint32_t*)&g_d2b[((size_t)b*MPAD + m0 + r)*Cq + c2*2] = 0u;
        }
        return;
    }

    int tx = tid & 31, ty = tid >> 5;
    #pragma unroll 8
    for (int q = 0; q < 32; q++) {
        int c = q*8 + ty;
        tile[c][tx] = desc2[((size_t)b*Cq + c)*HWq + m0 + tx];
    }
    __syncthreads();
    float ss = 0.f;
    #pragma unroll
    for (int i = 0; i < 32; i++) { float v = tile[ty*32 + i][tx]; ss += v*v; }
    part[ty][tx] = ss;
    __syncthreads();
    if (tid < 32) {
        float tot = 0.f;
        #pragma unroll
        for (int j = 0; j < 8; j++) tot += part[j][tid];
        sinv[tid] = 1.0f / sqrtf(tot + 1e-8f);
    }
    __syncthreads();
    #pragma unroll 4
    for (int r = 0; r < 32; r++) {
        float v = tile[tid][r];
        g_d2t[((size_t)b*HWq + m0 + r)*Cq + tid] = v;
        g_d2b[((size_t)b*MPAD + m0 + r)*Cq + tid] = __float2bfloat16(v * sinv[r]);
    }
}

// ---------------- K0: warp-per-row kd normalize + bilinear pos + nbr --------
__global__ void k_kd_pos(const float* __restrict__ kp1_desc,
                         const float* __restrict__ w_kp1,
                         const float* __restrict__ kp1,
                         const float* __restrict__ homo) {
    int row = blockIdx.x * 8 + (threadIdx.x >> 5);   // 8 warps/block
    int lane = threadIdx.x & 31;
    int b = row / Nq;

    // 8 channels per lane
    float v[8];
    *(float4*)&v[0] = *(const float4*)&kp1_desc[(size_t)row*Cq + lane*8];
    *(float4*)&v[4] = *(const float4*)&kp1_desc[(size_t)row*Cq + lane*8 + 4];
    float ss = 0.f;
    #pragma unroll
    for (int i = 0; i < 8; i++) ss += v[i]*v[i];
    ss = wred_sum(ss);
    float invk = 1.0f / sqrtf(ss + 1e-8f);

    __nv_bfloat16 kb[8];
    #pragma unroll
    for (int i = 0; i < 8; i++) kb[i] = __float2bfloat16(v[i]*invk);
    *(uint4*)&g_kdb[(size_t)row*Cq + lane*8] = *(uint4*)kb;

    float x = w_kp1[row*2 + 0] * 0.125f - 0.5f;
    float y = w_kp1[row*2 + 1] * 0.125f - 0.5f;
    float fx = floorf(x), fy = floorf(y);
    float wx = x - fx, wy = y - fy;
    int x0 = min(max((int)fx, 0), Wq - 1);
    int x1 = min(x0 + 1, Wq - 1);
    int y0 = min(max((int)fy, 0), Hq - 1);
    int y1 = min(y0 + 1, Hq - 1);
    const float* D = g_d2t + (size_t)b*HWq*Cq;
    const float* p00 = &D[(size_t)(y0*Wq + x0)*Cq + lane*8];
    const float* p01 = &D[(size_t)(y0*Wq + x1)*Cq + lane*8];
    const float* p10 = &D[(size_t)(y1*Wq + x0)*Cq + lane*8];
    const float* p11 = &D[(size_t)(y1*Wq + x1)*Cq + lane*8];
    float ws = 0.f, vw = 0.f;
    #pragma unroll
    for (int h = 0; h < 2; h++) {
        float4 a00 = *(const float4*)(p00 + h*4);
        float4 a01 = *(const float4*)(p01 + h*4);
        float4 a10 = *(const float4*)(p10 + h*4);
        float4 a11 = *(const float4*)(p11 + h*4);
        float c00[4] = {a00.x, a00.y, a00.z, a00.w};
        float c01[4] = {a01.x, a01.y, a01.z, a01.w};
        float c10[4] = {a10.x, a10.y, a10.z, a10.w};
        float c11[4] = {a11.x, a11.y, a11.z, a11.w};
        #pragma unroll
        for (int i = 0; i < 4; i++) {
            float top = c00[i]*(1.f - wx) + c01[i]*wx;
            float bot = c10[i]*(1.f - wx) + c11[i]*wx;
            float wv = top*(1.f - wy) + bot*wy;
            ws += wv*wv;
            vw += v[h*4 + i]*wv;
        }
    }
    ws = wred_sum(ws);
    vw = wred_sum(vw);
    if (lane == 0) {
        float invw = 1.0f / sqrtf(ws + 1e-8f);
        g_pos[row] = 2.0f - 2.0f*(vw*invk*invw);
    }

    // fused neighbourhood ids: lanes 0-3 each handle one q
    if (lane < 4) {
        float px = kp1[row*2], py = kp1[row*2 + 1];
        const float* Hm = homo + b*9;
        int idx4[4];
        top4cells(px, py, idx4);
        int ci = idx4[lane];
        int iy = ci / Wq, ix = ci % Wq;
        float cx = (ix + 0.5f)*GS, cy = (iy + 0.5f)*GS;
        float X = Hm[0]*cx + Hm[1]*cy + Hm[2];
        float Y = Hm[3]*cx + Hm[4]*cy + Hm[5];
        float Z = Hm[6]*cx + Hm[7]*cy + Hm[8];
        float wxp = X / (Z + 1e-8f);
        float wyp = Y / (Z + 1e-8f);
        top4cells(wxp, wyp, &g_nbr[(size_t)row*16 + lane*4]);
    }
}

// ---------------- K3: bf16 m16n8k16 GEMM, cp.async 2-stage, ldmatrix --------
// Block 128 rows x 128 cols, 8 warps (2x4), warp tile 64x32.
// Dynamic smem: A0,B0,A1,B1 tiles of 128 rows x 144B.  Fused top-4 epilogue.
__global__ __launch_bounds__(256, 2) void k_gemm_bf16() {
    extern __shared__ char dsm[];
    __shared__ uint32_t mask[128][4];
    uint32_t sbase = s2u(dsm);

    int bm = blockIdx.x, bn = blockIdx.y, b = blockIdx.z;
    int tid = threadIdx.x;
    int lane = tid & 31, warp = tid >> 5;
    int wy = warp & 1, wx = warp >> 1;      // 2 x 4 warp grid
    int wrow = wy * 64, wcol = wx * 32;
    int g = lane >> 2, tig = lane & 3;
    int n0 = bn * 128, m0 = bm * 128;
    const __nv_bfloat16* A  = g_kdb + (size_t)b*Nq*Cq;
    const __nv_bfloat16* Bt = g_d2b + (size_t)b*MPAD*Cq;

    int crow = tid >> 3, c16 = tid & 7;     // copy mapping (x4 rows per h)
    // prefetch both buffers up-front
    #pragma unroll
    for (int kc = 0; kc < 2; kc++) {
        uint32_t aT = sbase + kc*2*TILEB;
        uint32_t bT = aT + TILEB;
        #pragma unroll
        for (int h = 0; h < 4; h++) {
            int row = crow + h*32;
            cpa16(aT + row*144 + c16*16, &A [(size_t)(n0 + row)*Cq + kc*64 + c16*8]);
            cpa16(bT + row*144 + c16*16, &Bt[(size_t)(m0 + row)*Cq + kc*64 + c16*8]);
        }
        asm volatile("cp.async.commit_group;" ::: "memory");
    }

    // penalty bitmask for this block's 128 rows x 128 local cols
    if (tid < 128) { mask[tid][0] = 0; mask[tid][1] = 0; mask[tid][2] = 0; mask[tid][3] = 0; }
    __syncthreads();
    {
        int row = tid >> 1;
        int qb  = (tid & 1) * 8;
        const int* nb = &g_nbr[(size_t)(b*Nq + n0 + row)*16];
        #pragma unroll
        for (int q = 0; q < 8; q++) {
            int loc = nb[qb + q] - m0;
            if (loc >= 0 && loc < 128)
                atomicOr(&mask[row][loc >> 5], 1u << (loc & 31));
        }
    }

    float c[4][4][4];
    #pragma unroll
    for (int mt = 0; mt < 4; mt++)
        #pragma unroll
        for (int nt = 0; nt < 4; nt++)
            #pragma unroll
            for (int r = 0; r < 4; r++) c[mt][nt][r] = 0.f;

    #pragma unroll
    for (int kc = 0; kc < 4; kc++) {
        if (kc < 3) asm volatile("cp.async.wait_group 1;" ::: "memory");
        else        asm volatile("cp.async.wait_group 0;" ::: "memory");
        __syncthreads();
        int buf = kc & 1;
        uint32_t aB = sbase + buf*2*TILEB;
        uint32_t bB = aB + TILEB;
        #pragma unroll
        for (int ks = 0; ks < 4; ks++) {
            int sk = ks * 16;
            uint32_t af[4][4], bf[4][2];
            #pragma unroll
            for (int mt = 0; mt < 4; mt++)
                ldsm_x4(af[mt], aB + (wrow + mt*16 + (lane & 15))*144
                                   + (sk + ((lane >> 4) << 3))*2);
            #pragma unroll
            for (int p = 0; p < 2; p++) {
                int mi = lane >> 3;
                int ntl = p*2 + (mi >> 1);
                int kh = mi & 1;
                uint32_t r[4];
                ldsm_x4(r, bB + (wcol + ntl*8 + (lane & 7))*144 + (sk + kh*8)*2);
                bf[p*2][0] = r[0]; bf[p*2][1] = r[1];
                bf[p*2+1][0] = r[2]; bf[p*2+1][1] = r[3];
            }
            #pragma unroll
            for (int mt = 0; mt < 4; mt++)
                #pragma unroll
                for (int nt = 0; nt < 4; nt++) {
                    asm volatile(
                        "mma.sync.aligned.m16n8k16.row.col.f32.bf16.bf16.f32 "
                        "{%0,%1,%2,%3}, {%4,%5,%6,%7}, {%8,%9}, {%0,%1,%2,%3};"
                        : "+f"(c[mt][nt][0]), "+f"(c[mt][nt][1]),
                          "+f"(c[mt][nt][2]), "+f"(c[mt][nt][3])
                        : "r"(af[mt][0]), "r"(af[mt][1]), "r"(af[mt][2]), "r"(af[mt][3]),
                          "r"(bf[nt][0]), "r"(bf[nt][1]));
                }
        }
        __syncthreads();
        if (kc + 2 < 4) {   // refill the buffer just consumed
            uint32_t aT = sbase + buf*2*TILEB;
            uint32_t bT = aT + TILEB;
            #pragma unroll
            for (int h = 0; h < 4; h++) {
                int row = crow + h*32;
                cpa16(aT + row*144 + c16*16, &A [(size_t)(n0 + row)*Cq + (kc+2)*64 + c16*8]);
                cpa16(bT + row*144 + c16*16, &Bt[(size_t)(m0 + row)*Cq + (kc+2)*64 + c16*8]);
            }
            asm volatile("cp.async.commit_group;" ::: "memory");
        }
    }

    // ---- epilogue: per-thread running top-4 per row (sim = 2 - 2*acc) ----
    float t4[8][4];
    #pragma unroll
    for (int r = 0; r < 8; r++)
        #pragma unroll
        for (int s = 0; s < 4; s++) t4[r][s] = 1e30f;

    #pragma unroll
    for (int nt = 0; nt < 4; nt++) {
        int coll = wcol + nt*8 + tig*2;       // local col (even)
        int colg = m0 + coll;
        bool ok0 = colg < HWq, ok1 = (colg + 1) < HWq;
        #pragma unroll
        for (int mt = 0; mt < 4; mt++) {
            int lr0 = wrow + mt*16 + g;
            int lr1 = lr0 + 8;
            float v00 = 2.f - 2.f*c[mt][nt][0];
            float v01 = 2.f - 2.f*c[mt][nt][1];
            float v10 = 2.f - 2.f*c[mt][nt][2];
            float v11 = 2.f - 2.f*c[mt][nt][3];
            uint32_t m0b0 = mask[lr0][coll >> 5], m0b1 = mask[lr0][(coll+1) >> 5];
            uint32_t m1b0 = mask[lr1][coll >> 5], m1b1 = mask[lr1][(coll+1) >> 5];
            if (ok0 && !((m0b0 >> (coll & 31)) & 1))       ins4(t4[mt*2],     v00);
            if (ok1 && !((m0b1 >> ((coll+1) & 31)) & 1))   ins4(t4[mt*2],     v01);
            if (ok0 && !((m1b0 >> (coll & 31)) & 1))       ins4(t4[mt*2 + 1], v10);
            if (ok1 && !((m1b1 >> ((coll+1) & 31)) & 1))   ins4(t4[mt*2 + 1], v11);
        }
    }

    // ---- block reduction in reused dynamic smem: 64 cands -> top-4 per row --
    float* red = (float*)dsm;   // [128][64]
    __syncthreads();
    #pragma unroll
    for (int mt = 0; mt < 4; mt++) {
        int lr0 = wrow + mt*16 + g;
        int slot = (wx*4 + tig) * 4;
        *(float4*)&red[(lr0    )*64 + slot] = *(float4*)t4[mt*2];
        *(float4*)&red[(lr0 + 8)*64 + slot] = *(float4*)t4[mt*2 + 1];
    }
    __syncthreads();
    if (tid < 128) {
        float tt[4] = {1e30f, 1e30f, 1e30f, 1e30f};
        const float* r = &red[tid*64];
        #pragma unroll 8
        for (int q = 0; q < 64; q++) ins4(tt, r[q]);
        *(float4*)&g_part[((size_t)(b*Nq + n0 + tid)*NSPLIT + bm)*4] =
            make_float4(tt[0], tt[1], tt[2], tt[3]);
    }
}

// ---------------- K4: merge per-split partials (vectorized), hinge ----------
// one warp per row, 8 warps/block; 152 contiguous candidates = 38 float4.
// Stored quads are sorted ascending -> early-out when v.x >= current max.
__global__ __launch_bounds__(256) void k_merge() {
    int row = blockIdx.x * 8 + (threadIdx.x >> 5);
    int lane = threadIdx.x & 31;
    const float4* p = (const float4*)&g_part[(size_t)row*NSPLIT*4];
    float t[4] = {1e30f, 1e30f, 1e30f, 1e30f};
    #pragma unroll 2
    for (int i = lane; i < NSPLIT; i += 32) {
        float4 v = p[i];
        if (v.x >= t[3]) continue;      // whole quad can't contribute
        ins4(t, v.x); ins4(t, v.y); ins4(t, v.z); ins4(t, v.w);
    }
    #pragma unroll
    for (int off = 16; off > 0; off >>= 1) {
        float o0 = __shfl_xor_sync(0xffffffffu, t[0], off);
        float o1 = __shfl_xor_sync(0xffffffffu, t[1], off);
        float o2 = __shfl_xor_sync(0xffffffffu, t[2], off);
        float o3 = __shfl_xor_sync(0xffffffffu, t[3], off);
        float a[4] = {t[0], t[1], t[2], t[3]};
        float o[4] = {o0, o1, o2, o3};
        int ia = 0, ib = 0;
        #pragma unroll
        for (int k = 0; k < 4; k++) {
            float av = (ia < 4) ? a[ia] : 1e30f;
            float bv = (ib < 4) ? o[ib] : 1e30f;
            if (av <= bv) { t[k] = av; ia++; } else { t[k] = bv; ib++; }
        }
    }
    if (lane == 0) {
        float pos = g_pos[row];
        float lsum = 0.f;
        #pragma unroll
        for (int r = 0; r < 4; r++) lsum += fmaxf(pos - t[r] + 1.0f, 0.f);
        g_rowloss[row] = lsum;
    }
}

// ---------------- K5: deterministic final mean ------------------------------
__global__ void k_final(float* out) {
    __shared__ float red[256];
    int tid = threadIdx.x;
    float acc = 0.f;
    for (int i = tid; i < Bq*Nq; i += 256) acc += g_rowloss[i];
    red[tid] = acc; __syncthreads();
    for (int s = 128; s > 0; s >>= 1) {
        if (tid < s) red[tid] += red[tid + s];
        __syncthreads();
    }
    if (tid == 0) out[0] = red[0] / (float)(Bq*Nq*NUM_NEG);
}

// ---------------- launch ----------------------------------------------------
extern "C" void kernel_launch(void* const* d_in, const int* in_sizes, int n_in,
                              void* d_out, int out_size) {
    const float* kp1      = (const float*)d_in[0];
    const float* w_kp1    = (const float*)d_in[1];
    const float* kp1_desc = (const float*)d_in[2];
    const float* desc2    = (const float*)d_in[3];
    const float* homo     = (const float*)d_in[4];
    float* out = (float*)d_out;

    cudaFuncSetAttribute(k_gemm_bf16, cudaFuncAttributeMaxDynamicSharedMemorySize, SMEM_GEMM);

    k_prep<<<dim3(MPAD/32, Bq), 256>>>(desc2);
    k_kd_pos<<<Bq*Nq/8, 256>>>(kp1_desc, w_kp1, kp1, homo);
    k_gemm_bf16<<<dim3(NSPLIT, Nq/128, Bq), 256, SMEM_GEMM>>>();
    k_merge<<<Bq*Nq/8, 256>>>();
    k_final<<<1, 256>>>(out);
}

// round 13
// speedup vs baseline: 1.2480x; 1.0179x over previous
#include <cuda_runtime.h>
#include <cuda_bf16.h>
#include <math.h>
#include <stdint.h>

#define Bq 4
#define Nq 1024
#define Cq 256
#define Hq 60
#define Wq 80
#define HWq (Hq*Wq)          // 4800
#define GS 8.0f
#define NUM_NEG 4
#define NSPLIT 38            // ceil(4800/128) col splits
#define MPAD (NSPLIT*128)    // 4864 padded cols
#define TILEB 18432          // 128 rows * 144B
#define SMEM_GEMM (6*TILEB)  // 3-stage x (A,B) = 110592 B

// ---------------- scratch (device globals; no allocs allowed) ----------------
__device__ float g_d2t[Bq*HWq*Cq];            // raw desc2 transposed [b][m][c]
__device__ __nv_bfloat16 g_kdb[Bq*Nq*Cq];     // normalized kp1 desc, bf16
__device__ __nv_bfloat16 g_d2b[Bq*MPAD*Cq];   // normalized desc2, bf16, padded
__device__ float g_pos[Bq*Nq];
__device__ int   g_nbr[Bq*Nq*16];             // 16 penalized cell ids per row
__device__ float g_part[Bq*Nq*NSPLIT*4];      // per-split partial top-4
__device__ float g_rowloss[Bq*Nq];
__device__ int   g_ctr;                       // last-block counter for k_merge

// ---------------- helpers ----------------
__device__ __forceinline__ void ins4(float* t, float v) {
    if (v < t[3]) {
        if (v < t[2]) {
            t[3] = t[2];
            if (v < t[1]) { t[2] = t[1]; if (v < t[0]) { t[1] = t[0]; t[0] = v; } else t[1] = v; }
            else t[2] = v;
        } else t[3] = v;
    }
}
__device__ __forceinline__ uint32_t s2u(const void* p) {
    uint32_t a;
    asm("{ .reg .u64 t; cvta.to.shared.u64 t, %1; cvt.u32.u64 %0, t; }" : "=r"(a) : "l"(p));
    return a;
}
__device__ __forceinline__ void cpa16(uint32_t dst, const void* src) {
    asm volatile("cp.async.cg.shared.global [%0], [%1], 16;" :: "r"(dst), "l"(src));
}
__device__ __forceinline__ void ldsm_x4(uint32_t* r, uint32_t addr) {
    asm volatile("ldmatrix.sync.aligned.m8n8.x4.shared.b16 {%0,%1,%2,%3}, [%4];"
                 : "=r"(r[0]), "=r"(r[1]), "=r"(r[2]), "=r"(r[3]) : "r"(addr));
}
__device__ __forceinline__ float wred_sum(float v) {
    #pragma unroll
    for (int o = 16; o > 0; o >>= 1) v += __shfl_xor_sync(0xffffffffu, v, o);
    return v;
}

// 4 nearest grid centers to (px,py): compares clip(aa+bb-2ab, 1e-12) — the
// reference's sqrt is strictly monotone on this value, so ordering and
// tie-breaking (lower index first) are identical.  Nearest 4 centers always
// lie in a clamped 5x5 window around floor(p/8).
__device__ void top4cells(float px, float py, int* out) {
    int cx0 = (int)floorf(px * 0.125f);
    int cy0 = (int)floorf(py * 0.125f);
    int lx = min(max(cx0 - 2, 0), Wq - 5);
    int ly = min(max(cy0 - 2, 0), Hq - 5);
    float bd0 = 1e30f, bd1 = 1e30f, bd2 = 1e30f, bd3 = 1e30f;
    int   bi0 = -1, bi1 = -1, bi2 = -1, bi3 = -1;
    float aa = px*px + py*py;
    for (int yy = ly; yy < ly + 5; yy++) {
        float cy = (yy + 0.5f) * GS;
        for (int xx = lx; xx < lx + 5; xx++) {
            float cx = (xx + 0.5f) * GS;
            float bb = cx*cx + cy*cy;
            float ab = px*cx + py*cy;
            float d = fmaxf(aa + bb - 2.0f*ab, 1e-12f);
            int id = yy * Wq + xx;
            if (d < bd3) {
                if (d < bd2) {
                    bd3 = bd2; bi3 = bi2;
                    if (d < bd1) {
                        bd2 = bd1; bi2 = bi1;
                        if (d < bd0) { bd1 = bd0; bi1 = bi0; bd0 = d; bi0 = id; }
                        else         { bd1 = d; bi1 = id; }
                    } else { bd2 = d; bi2 = id; }
                } else { bd3 = d; bi3 = id; }
            }
        }
    }
    out[0] = bi0; out[1] = bi1; out[2] = bi2; out[3] = bi3;
}

// ---------------- K1: fused norms + transpose + bf16 normalize --------------
__global__ void k_prep(const float* __restrict__ desc2) {
    __shared__ float tile[256][33];
    __shared__ float part[8][33];
    __shared__ float sinv[32];
    int b = blockIdx.y;
    int m0 = blockIdx.x * 32;
    int tid = threadIdx.x;

    if (blockIdx.x == 0 && b == 0 && tid == 0) g_ctr = 0;   // reset merge counter

    if (m0 >= HWq) {     // padding rows of g_d2b -> zeros
        for (int i = tid; i < 32*Cq/2; i += 256) {
            int r = i / (Cq/2), c2 = i % (Cq/2);
            *(uint32_t*)&g_d2b[((size_t)b*MPAD + m0 + r)*Cq + c2*2] = 0u;
        }
        return;
    }

    int tx = tid & 31, ty = tid >> 5;
    #pragma unroll 8
    for (int q = 0; q < 32; q++) {
        int c = q*8 + ty;
        tile[c][tx] = desc2[((size_t)b*Cq + c)*HWq + m0 + tx];
    }
    __syncthreads();
    float ss = 0.f;
    #pragma unroll
    for (int i = 0; i < 32; i++) { float v = tile[ty*32 + i][tx]; ss += v*v; }
    part[ty][tx] = ss;
    __syncthreads();
    if (tid < 32) {
        float tot = 0.f;
        #pragma unroll
        for (int j = 0; j < 8; j++) tot += part[j][tid];
        sinv[tid] = 1.0f / sqrtf(tot + 1e-8f);
    }
    __syncthreads();
    #pragma unroll 4
    for (int r = 0; r < 32; r++) {
        float v = tile[tid][r];
        g_d2t[((size_t)b*HWq + m0 + r)*Cq + tid] = v;
        g_d2b[((size_t)b*MPAD + m0 + r)*Cq + tid] = __float2bfloat16(v * sinv[r]);
    }
}

// ---------------- K0: warp-per-row kd normalize + bilinear pos + nbr --------
__global__ void k_kd_pos(const float* __restrict__ kp1_desc,
                         const float* __restrict__ w_kp1,
                         const float* __restrict__ kp1,
                         const float* __restrict__ homo) {
    int row = blockIdx.x * 8 + (threadIdx.x >> 5);   // 8 warps/block
    int lane = threadIdx.x & 31;
    int b = row / Nq;

    // 8 channels per lane
    float v[8];
    *(float4*)&v[0] = *(const float4*)&kp1_desc[(size_t)row*Cq + lane*8];
    *(float4*)&v[4] = *(const float4*)&kp1_desc[(size_t)row*Cq + lane*8 + 4];
    float ss = 0.f;
    #pragma unroll
    for (int i = 0; i < 8; i++) ss += v[i]*v[i];
    ss = wred_sum(ss);
    float invk = 1.0f / sqrtf(ss + 1e-8f);

    __nv_bfloat16 kb[8];
    #pragma unroll
    for (int i = 0; i < 8; i++) kb[i] = __float2bfloat16(v[i]*invk);
    *(uint4*)&g_kdb[(size_t)row*Cq + lane*8] = *(uint4*)kb;

    float x = w_kp1[row*2 + 0] * 0.125f - 0.5f;
    float y = w_kp1[row*2 + 1] * 0.125f - 0.5f;
    float fx = floorf(x), fy = floorf(y);
    float wx = x - fx, wy = y - fy;
    int x0 = min(max((int)fx, 0), Wq - 1);
    int x1 = min(x0 + 1, Wq - 1);
    int y0 = min(max((int)fy, 0), Hq - 1);
    int y1 = min(y0 + 1, Hq - 1);
    const float* D = g_d2t + (size_t)b*HWq*Cq;
    const float* p00 = &D[(size_t)(y0*Wq + x0)*Cq + lane*8];
    const float* p01 = &D[(size_t)(y0*Wq + x1)*Cq + lane*8];
    const float* p10 = &D[(size_t)(y1*Wq + x0)*Cq + lane*8];
    const float* p11 = &D[(size_t)(y1*Wq + x1)*Cq + lane*8];
    float ws = 0.f, vw = 0.f;
    #pragma unroll
    for (int h = 0; h < 2; h++) {
        float4 a00 = *(const float4*)(p00 + h*4);
        float4 a01 = *(const float4*)(p01 + h*4);
        float4 a10 = *(const float4*)(p10 + h*4);
        float4 a11 = *(const float4*)(p11 + h*4);
        float c00[4] = {a00.x, a00.y, a00.z, a00.w};
        float c01[4] = {a01.x, a01.y, a01.z, a01.w};
        float c10[4] = {a10.x, a10.y, a10.z, a10.w};
        float c11[4] = {a11.x, a11.y, a11.z, a11.w};
        #pragma unroll
        for (int i = 0; i < 4; i++) {
            float top = c00[i]*(1.f - wx) + c01[i]*wx;
            float bot = c10[i]*(1.f - wx) + c11[i]*wx;
            float wv = top*(1.f - wy) + bot*wy;
            ws += wv*wv;
            vw += v[h*4 + i]*wv;
        }
    }
    ws = wred_sum(ws);
    vw = wred_sum(vw);
    if (lane == 0) {
        float invw = 1.0f / sqrtf(ws + 1e-8f);
        g_pos[row] = 2.0f - 2.0f*(vw*invk*invw);
    }

    // fused neighbourhood ids: lanes 0-3 each handle one q
    if (lane < 4) {
        float px = kp1[row*2], py = kp1[row*2 + 1];
        const float* Hm = homo + b*9;
        int idx4[4];
        top4cells(px, py, idx4);
        int ci = idx4[lane];
        int iy = ci / Wq, ix = ci % Wq;
        float cx = (ix + 0.5f)*GS, cy = (iy + 0.5f)*GS;
        float X = Hm[0]*cx + Hm[1]*cy + Hm[2];
        float Y = Hm[3]*cx + Hm[4]*cy + Hm[5];
        float Z = Hm[6]*cx + Hm[7]*cy + Hm[8];
        float wxp = X / (Z + 1e-8f);
        float wyp = Y / (Z + 1e-8f);
        top4cells(wxp, wyp, &g_nbr[(size_t)row*16 + lane*4]);
    }
}

// ---------------- K3: bf16 m16n8k16 GEMM, cp.async 3-stage, ldmatrix --------
// Block 128 rows x 128 cols, 8 warps (2x4), warp tile 64x32.
// Dynamic smem: 3 stages of (A,B) tiles, 128 rows x 144B.  Fused top-4 epi.
__global__ __launch_bounds__(256, 2) void k_gemm_bf16() {
    extern __shared__ char dsm[];
    __shared__ uint32_t mask[128][4];
    uint32_t sbase = s2u(dsm);

    int bm = blockIdx.x, bn = blockIdx.y, b = blockIdx.z;
    int tid = threadIdx.x;
    int lane = tid & 31, warp = tid >> 5;
    int wy = warp & 1, wx = warp >> 1;      // 2 x 4 warp grid
    int wrow = wy * 64, wcol = wx * 32;
    int g = lane >> 2, tig = lane & 3;
    int n0 = bn * 128, m0 = bm * 128;
    const __nv_bfloat16* A  = g_kdb + (size_t)b*Nq*Cq;
    const __nv_bfloat16* Bt = g_d2b + (size_t)b*MPAD*Cq;

    int crow = tid >> 3, c16 = tid & 7;     // copy mapping (x4 rows per h)
    // prefetch stages 0..2 (chunks 0..2)
    #pragma unroll
    for (int kc = 0; kc < 3; kc++) {
        uint32_t aT = sbase + kc*2*TILEB;
        uint32_t bT = aT + TILEB;
        #pragma unroll
        for (int h = 0; h < 4; h++) {
            int row = crow + h*32;
            cpa16(aT + row*144 + c16*16, &A [(size_t)(n0 + row)*Cq + kc*64 + c16*8]);
            cpa16(bT + row*144 + c16*16, &Bt[(size_t)(m0 + row)*Cq + kc*64 + c16*8]);
        }
        asm volatile("cp.async.commit_group;" ::: "memory");
    }

    // penalty bitmask for this block's 128 rows x 128 local cols
    if (tid < 128) { mask[tid][0] = 0; mask[tid][1] = 0; mask[tid][2] = 0; mask[tid][3] = 0; }
    __syncthreads();
    {
        int row = tid >> 1;
        int qb  = (tid & 1) * 8;
        const int* nb = &g_nbr[(size_t)(b*Nq + n0 + row)*16];
        #pragma unroll
        for (int q = 0; q < 8; q++) {
            int loc = nb[qb + q] - m0;
            if (loc >= 0 && loc < 128)
                atomicOr(&mask[row][loc >> 5], 1u << (loc & 31));
        }
    }

    float c[4][4][4];
    #pragma unroll
    for (int mt = 0; mt < 4; mt++)
        #pragma unroll
        for (int nt = 0; nt < 4; nt++)
            #pragma unroll
            for (int r = 0; r < 4; r++) c[mt][nt][r] = 0.f;

    #pragma unroll
    for (int kc = 0; kc < 4; kc++) {
        // groups committed before iter kc: 3 + (kc>=1); need chunks 0..kc done
        if (kc <= 1)      asm volatile("cp.async.wait_group 2;" ::: "memory");
        else if (kc == 2) asm volatile("cp.async.wait_group 1;" ::: "memory");
        else              asm volatile("cp.async.wait_group 0;" ::: "memory");
        __syncthreads();
        int buf = kc % 3;
        uint32_t aB = sbase + buf*2*TILEB;
        uint32_t bB = aB + TILEB;
        #pragma unroll
        for (int ks = 0; ks < 4; ks++) {
            int sk = ks * 16;
            uint32_t af[4][4], bf[4][2];
            #pragma unroll
            for (int mt = 0; mt < 4; mt++)
                ldsm_x4(af[mt], aB + (wrow + mt*16 + (lane & 15))*144
                                   + (sk + ((lane >> 4) << 3))*2);
            #pragma unroll
            for (int p = 0; p < 2; p++) {
                int mi = lane >> 3;
                int ntl = p*2 + (mi >> 1);
                int kh = mi & 1;
                uint32_t r[4];
                ldsm_x4(r, bB + (wcol + ntl*8 + (lane & 7))*144 + (sk + kh*8)*2);
                bf[p*2][0] = r[0]; bf[p*2][1] = r[1];
                bf[p*2+1][0] = r[2]; bf[p*2+1][1] = r[3];
            }
            #pragma unroll
            for (int mt = 0; mt < 4; mt++)
                #pragma unroll
                for (int nt = 0; nt < 4; nt++) {
                    asm volatile(
                        "mma.sync.aligned.m16n8k16.row.col.f32.bf16.bf16.f32 "
                        "{%0,%1,%2,%3}, {%4,%5,%6,%7}, {%8,%9}, {%0,%1,%2,%3};"
                        : "+f"(c[mt][nt][0]), "+f"(c[mt][nt][1]),
                          "+f"(c[mt][nt][2]), "+f"(c[mt][nt][3])
                        : "r"(af[mt][0]), "r"(af[mt][1]), "r"(af[mt][2]), "r"(af[mt][3]),
                          "r"(bf[nt][0]), "r"(bf[nt][1]));
                }
        }
        __syncthreads();
        if (kc == 0) {      // refill stage 0 with chunk 3
            uint32_t aT = sbase;
            uint32_t bT = sbase + TILEB;
            #pragma unroll
            for (int h = 0; h < 4; h++) {
                int row = crow + h*32;
                cpa16(aT + row*144 + c16*16, &A [(size_t)(n0 + row)*Cq + 3*64 + c16*8]);
                cpa16(bT + row*144 + c16*16, &Bt[(size_t)(m0 + row)*Cq + 3*64 + c16*8]);
            }
            asm volatile("cp.async.commit_group;" ::: "memory");
        }
    }

    // ---- epilogue: per-thread running top-4 per row (sim = 2 - 2*acc) ----
    float t4[8][4];
    #pragma unroll
    for (int r = 0; r < 8; r++)
        #pragma unroll
        for (int s = 0; s < 4; s++) t4[r][s] = 1e30f;

    #pragma unroll
    for (int nt = 0; nt < 4; nt++) {
        int coll = wcol + nt*8 + tig*2;       // local col (even)
        int colg = m0 + coll;
        bool ok0 = colg < HWq, ok1 = (colg + 1) < HWq;
        #pragma unroll
        for (int mt = 0; mt < 4; mt++) {
            int lr0 = wrow + mt*16 + g;
            int lr1 = lr0 + 8;
            float v00 = 2.f - 2.f*c[mt][nt][0];
            float v01 = 2.f - 2.f*c[mt][nt][1];
            float v10 = 2.f - 2.f*c[mt][nt][2];
            float v11 = 2.f - 2.f*c[mt][nt][3];
            uint32_t m0b0 = mask[lr0][coll >> 5], m0b1 = mask[lr0][(coll+1) >> 5];
            uint32_t m1b0 = mask[lr1][coll >> 5], m1b1 = mask[lr1][(coll+1) >> 5];
            if (ok0 && !((m0b0 >> (coll & 31)) & 1))       ins4(t4[mt*2],     v00);
            if (ok1 && !((m0b1 >> ((coll+1) & 31)) & 1))   ins4(t4[mt*2],     v01);
            if (ok0 && !((m1b0 >> (coll & 31)) & 1))       ins4(t4[mt*2 + 1], v10);
            if (ok1 && !((m1b1 >> ((coll+1) & 31)) & 1))   ins4(t4[mt*2 + 1], v11);
        }
    }

    // ---- block reduction in reused dynamic smem: 64 cands -> top-4 per row --
    float* red = (float*)dsm;   // [128][64]
    __syncthreads();
    #pragma unroll
    for (int mt = 0; mt < 4; mt++) {
        int lr0 = wrow + mt*16 + g;
        int slot = (wx*4 + tig) * 4;
        *(float4*)&red[(lr0    )*64 + slot] = *(float4*)t4[mt*2];
        *(float4*)&red[(lr0 + 8)*64 + slot] = *(float4*)t4[mt*2 + 1];
    }
    __syncthreads();
    if (tid < 128) {
        float tt[4] = {1e30f, 1e30f, 1e30f, 1e30f};
        const float* r = &red[tid*64];
        #pragma unroll 8
        for (int q = 0; q < 64; q++) ins4(tt, r[q]);
        *(float4*)&g_part[((size_t)(b*Nq + n0 + tid)*NSPLIT + bm)*4] =
            make_float4(tt[0], tt[1], tt[2], tt[3]);
    }
}

// ---------------- K4: merge partials + hinge + fused final mean -------------
// one warp per row, 8 warps/block; last finishing block does the global mean.
__global__ __launch_bounds__(256) void k_merge(float* out) {
    int row = blockIdx.x * 8 + (threadIdx.x >> 5);
    int lane = threadIdx.x & 31;
    const float4* p = (const float4*)&g_part[(size_t)row*NSPLIT*4];
    float t[4] = {1e30f, 1e30f, 1e30f, 1e30f};
    #pragma unroll 2
    for (int i = lane; i < NSPLIT; i += 32) {
        float4 v = p[i];
        if (v.x >= t[3]) continue;      // sorted quad can't contribute
        ins4(t, v.x); ins4(t, v.y); ins4(t, v.z); ins4(t, v.w);
    }
    #pragma unroll
    for (int off = 16; off > 0; off >>= 1) {
        float o0 = __shfl_xor_sync(0xffffffffu, t[0], off);
        float o1 = __shfl_xor_sync(0xffffffffu, t[1], off);
        float o2 = __shfl_xor_sync(0xffffffffu, t[2], off);
        float o3 = __shfl_xor_sync(0xffffffffu, t[3], off);
        float a[4] = {t[0], t[1], t[2], t[3]};
        float o[4] = {o0, o1, o2, o3};
        int ia = 0, ib = 0;
        #pragma unroll
        for (int k = 0; k < 4; k++) {
            float av = (ia < 4) ? a[ia] : 1e30f;
            float bv = (ib < 4) ? o[ib] : 1e30f;
            if (av <= bv) { t[k] = av; ia++; } else { t[k] = bv; ib++; }
        }
    }
    if (lane == 0) {
        float pos = g_pos[row];
        float lsum = 0.f;
        #pragma unroll
        for (int r = 0; r < 4; r++) lsum += fmaxf(pos - t[r] + 1.0f, 0.f);
        g_rowloss[row] = lsum;
    }

    // fused final mean: last block to finish sums all rows (deterministic order)
    __shared__ bool last;
    __shared__ float red[256];
    __threadfence();
    if (threadIdx.x == 0)
        last = (atomicAdd(&g_ctr, 1) == (int)gridDim.x - 1);
    __syncthreads();
    if (last) {
        int tid = threadIdx.x;
        float acc = 0.f;
        for (int i = tid; i < Bq*Nq; i += 256) acc += g_rowloss[i];
        red[tid] = acc; __syncthreads();
        #pragma unroll
        for (int s = 128; s > 0; s >>= 1) {
            if (tid < s) red[tid] += red[tid + s];
            __syncthreads();
        }
        if (tid == 0) out[0] = red[0] / (float)(Bq*Nq*NUM_NEG);
    }
}

// ---------------- launch ----------------------------------------------------
extern "C" void kernel_launch(void* const* d_in, const int* in_sizes, int n_in,
                              void* d_out, int out_size) {
    const float* kp1      = (const float*)d_in[0];
    const float* w_kp1    = (const float*)d_in[1];
    const float* kp1_desc = (const float*)d_in[2];
    const float* desc2    = (const float*)d_in[3];
    const float* homo     = (const float*)d_in[4];
    float* out = (float*)d_out;

    cudaFuncSetAttribute(k_gemm_bf16, cudaFuncAttributeMaxDynamicSharedMemorySize, SMEM_GEMM);

    k_prep<<<dim3(MPAD/32, Bq), 256>>>(desc2);
    k_kd_pos<<<Bq*Nq/8, 256>>>(kp1_desc, w_kp1, kp1, homo);
    k_gemm_bf16<<<dim3(NSPLIT, Nq/128, Bq), 256, SMEM_GEMM>>>();
    k_merge<<<Bq*Nq/8, 256>>>(out);
}

// round 14
// speedup vs baseline: 1.3084x; 1.0484x over previous
#include <cuda_runtime.h>
#include <cuda_bf16.h>
#include <math.h>
#include <stdint.h>

#define Bq 4
#define Nq 1024
#define Cq 256
#define Hq 60
#define Wq 80
#define HWq (Hq*Wq)          // 4800
#define GS 8.0f
#define NUM_NEG 4
#define NSPLIT 38            // ceil(4800/128) col splits
#define MPAD (NSPLIT*128)    // 4864 padded cols
#define TILEB 18432          // 128 rows * 144B
#define SMEM_GEMM (6*TILEB)  // 3-stage x (A,B) = 110592 B
#define MERGEBLKS (Bq*Nq/8)  // 512

// ---------------- scratch (device globals; no allocs allowed) ----------------
__device__ float g_d2t[Bq*HWq*Cq];            // raw desc2 transposed [b][m][c]
__device__ __nv_bfloat16 g_kdb[Bq*Nq*Cq];     // normalized kp1 desc, bf16
__device__ __nv_bfloat16 g_d2b[Bq*MPAD*Cq];   // normalized desc2, bf16, padded
__device__ float g_pos[Bq*Nq];
__device__ int   g_nbr[Bq*Nq*16];             // 16 penalized cell ids per row
__device__ float g_part[Bq*Nq*NSPLIT*4];      // per-split partial top-4
__device__ float g_bsum[MERGEBLKS];           // per-merge-block loss sums
__device__ int   g_ctr;                       // last-block counter for k_merge

// ---------------- helpers ----------------
__device__ __forceinline__ void ins4(float* t, float v) {
    if (v < t[3]) {
        if (v < t[2]) {
            t[3] = t[2];
            if (v < t[1]) { t[2] = t[1]; if (v < t[0]) { t[1] = t[0]; t[0] = v; } else t[1] = v; }
            else t[2] = v;
        } else t[3] = v;
    }
}
__device__ __forceinline__ uint32_t s2u(const void* p) {
    uint32_t a;
    asm("{ .reg .u64 t; cvta.to.shared.u64 t, %1; cvt.u32.u64 %0, t; }" : "=r"(a) : "l"(p));
    return a;
}
__device__ __forceinline__ void cpa16(uint32_t dst, const void* src) {
    asm volatile("cp.async.cg.shared.global [%0], [%1], 16;" :: "r"(dst), "l"(src));
}
__device__ __forceinline__ void ldsm_x4(uint32_t* r, uint32_t addr) {
    asm volatile("ldmatrix.sync.aligned.m8n8.x4.shared.b16 {%0,%1,%2,%3}, [%4];"
                 : "=r"(r[0]), "=r"(r[1]), "=r"(r[2]), "=r"(r[3]) : "r"(addr));
}
__device__ __forceinline__ float wred_sum(float v) {
    #pragma unroll
    for (int o = 16; o > 0; o >>= 1) v += __shfl_xor_sync(0xffffffffu, v, o);
    return v;
}

// 4 nearest grid centers to (px,py): compares clip(aa+bb-2ab, 1e-12) — the
// reference's sqrt is strictly monotone on this value, so ordering and
// tie-breaking (lower index first) are identical.  Nearest 4 centers always
// lie in a clamped 5x5 window around floor(p/8).
__device__ void top4cells(float px, float py, int* out) {
    int cx0 = (int)floorf(px * 0.125f);
    int cy0 = (int)floorf(py * 0.125f);
    int lx = min(max(cx0 - 2, 0), Wq - 5);
    int ly = min(max(cy0 - 2, 0), Hq - 5);
    float bd0 = 1e30f, bd1 = 1e30f, bd2 = 1e30f, bd3 = 1e30f;
    int   bi0 = -1, bi1 = -1, bi2 = -1, bi3 = -1;
    float aa = px*px + py*py;
    for (int yy = ly; yy < ly + 5; yy++) {
        float cy = (yy + 0.5f) * GS;
        for (int xx = lx; xx < lx + 5; xx++) {
            float cx = (xx + 0.5f) * GS;
            float bb = cx*cx + cy*cy;
            float ab = px*cx + py*cy;
            float d = fmaxf(aa + bb - 2.0f*ab, 1e-12f);
            int id = yy * Wq + xx;
            if (d < bd3) {
                if (d < bd2) {
                    bd3 = bd2; bi3 = bi2;
                    if (d < bd1) {
                        bd2 = bd1; bi2 = bi1;
                        if (d < bd0) { bd1 = bd0; bi1 = bi0; bd0 = d; bi0 = id; }
                        else         { bd1 = d; bi1 = id; }
                    } else { bd2 = d; bi2 = id; }
                } else { bd3 = d; bi3 = id; }
            }
        }
    }
    out[0] = bi0; out[1] = bi1; out[2] = bi2; out[3] = bi3;
}

// ---------------- K1: fused norms + transpose + bf16 normalize --------------
__global__ void k_prep(const float* __restrict__ desc2) {
    __shared__ float tile[256][33];
    __shared__ float part[8][33];
    __shared__ float sinv[32];
    int b = blockIdx.y;
    int m0 = blockIdx.x * 32;
    int tid = threadIdx.x;

    if (blockIdx.x == 0 && b == 0 && tid == 0) g_ctr = 0;   // reset merge counter

    if (m0 >= HWq) {     // padding rows of g_d2b -> zeros
        for (int i = tid; i < 32*Cq/2; i += 256) {
            int r = i / (Cq/2), c2 = i % (Cq/2);
            *(uint32_t*)&g_d2b[((size_t)b*MPAD + m0 + r)*Cq + c2*2] = 0u;
        }
        return;
    }

    int tx = tid & 31, ty = tid >> 5;
    #pragma unroll 8
    for (int q = 0; q < 32; q++) {
        int c = q*8 + ty;
        tile[c][tx] = desc2[((size_t)b*Cq + c)*HWq + m0 + tx];
    }
    __syncthreads();
    float ss = 0.f;
    #pragma unroll
    for (int i = 0; i < 32; i++) { float v = tile[ty*32 + i][tx]; ss += v*v; }
    part[ty][tx] = ss;
    __syncthreads();
    if (tid < 32) {
        float tot = 0.f;
        #pragma unroll
        for (int j = 0; j < 8; j++) tot += part[j][tid];
        sinv[tid] = 1.0f / sqrtf(tot + 1e-8f);
    }
    __syncthreads();
    #pragma unroll 4
    for (int r = 0; r < 32; r++) {
        float v = tile[tid][r];
        g_d2t[((size_t)b*HWq + m0 + r)*Cq + tid] = v;
        g_d2b[((size_t)b*MPAD + m0 + r)*Cq + tid] = __float2bfloat16(v * sinv[r]);
    }
}

// ---------------- K0: warp-per-row kd normalize + bilinear pos + nbr --------
__global__ void k_kd_pos(const float* __restrict__ kp1_desc,
                         const float* __restrict__ w_kp1,
                         const float* __restrict__ kp1,
                         const float* __restrict__ homo) {
    int row = blockIdx.x * 8 + (threadIdx.x >> 5);   // 8 warps/block
    int lane = threadIdx.x & 31;
    int b = row / Nq;

    // 8 channels per lane
    float v[8];
    *(float4*)&v[0] = *(const float4*)&kp1_desc[(size_t)row*Cq + lane*8];
    *(float4*)&v[4] = *(const float4*)&kp1_desc[(size_t)row*Cq + lane*8 + 4];
    float ss = 0.f;
    #pragma unroll
    for (int i = 0; i < 8; i++) ss += v[i]*v[i];
    ss = wred_sum(ss);
    float invk = 1.0f / sqrtf(ss + 1e-8f);

    __nv_bfloat16 kb[8];
    #pragma unroll
    for (int i = 0; i < 8; i++) kb[i] = __float2bfloat16(v[i]*invk);
    *(uint4*)&g_kdb[(size_t)row*Cq + lane*8] = *(uint4*)kb;

    float x = w_kp1[row*2 + 0] * 0.125f - 0.5f;
    float y = w_kp1[row*2 + 1] * 0.125f - 0.5f;
    float fx = floorf(x), fy = floorf(y);
    float wx = x - fx, wy = y - fy;
    int x0 = min(max((int)fx, 0), Wq - 1);
    int x1 = min(x0 + 1, Wq - 1);
    int y0 = min(max((int)fy, 0), Hq - 1);
    int y1 = min(y0 + 1, Hq - 1);
    const float* D = g_d2t + (size_t)b*HWq*Cq;
    const float* p00 = &D[(size_t)(y0*Wq + x0)*Cq + lane*8];
    const float* p01 = &D[(size_t)(y0*Wq + x1)*Cq + lane*8];
    const float* p10 = &D[(size_t)(y1*Wq + x0)*Cq + lane*8];
    const float* p11 = &D[(size_t)(y1*Wq + x1)*Cq + lane*8];
    float ws = 0.f, vw = 0.f;
    #pragma unroll
    for (int h = 0; h < 2; h++) {
        float4 a00 = *(const float4*)(p00 + h*4);
        float4 a01 = *(const float4*)(p01 + h*4);
        float4 a10 = *(const float4*)(p10 + h*4);
        float4 a11 = *(const float4*)(p11 + h*4);
        float c00[4] = {a00.x, a00.y, a00.z, a00.w};
        float c01[4] = {a01.x, a01.y, a01.z, a01.w};
        float c10[4] = {a10.x, a10.y, a10.z, a10.w};
        float c11[4] = {a11.x, a11.y, a11.z, a11.w};
        #pragma unroll
        for (int i = 0; i < 4; i++) {
            float top = c00[i]*(1.f - wx) + c01[i]*wx;
            float bot = c10[i]*(1.f - wx) + c11[i]*wx;
            float wv = top*(1.f - wy) + bot*wy;
            ws += wv*wv;
            vw += v[h*4 + i]*wv;
        }
    }
    ws = wred_sum(ws);
    vw = wred_sum(vw);
    if (lane == 0) {
        float invw = 1.0f / sqrtf(ws + 1e-8f);
        g_pos[row] = 2.0f - 2.0f*(vw*invk*invw);
    }

    // fused neighbourhood ids: lanes 0-3 each handle one q
    if (lane < 4) {
        float px = kp1[row*2], py = kp1[row*2 + 1];
        const float* Hm = homo + b*9;
        int idx4[4];
        top4cells(px, py, idx4);
        int ci = idx4[lane];
        int iy = ci / Wq, ix = ci % Wq;
        float cx = (ix + 0.5f)*GS, cy = (iy + 0.5f)*GS;
        float X = Hm[0]*cx + Hm[1]*cy + Hm[2];
        float Y = Hm[3]*cx + Hm[4]*cy + Hm[5];
        float Z = Hm[6]*cx + Hm[7]*cy + Hm[8];
        float wxp = X / (Z + 1e-8f);
        float wyp = Y / (Z + 1e-8f);
        top4cells(wxp, wyp, &g_nbr[(size_t)row*16 + lane*4]);
    }
}

// ---------------- K3: bf16 m16n8k16 GEMM, cp.async 3-stage, ldmatrix --------
// Block 128 rows x 128 cols, 8 warps (2x4), warp tile 64x32.
// Single __syncthreads per chunk (post-compute sync only before the one
// refill at kc==0).  Fused top-4 epilogue.
__global__ __launch_bounds__(256, 2) void k_gemm_bf16() {
    extern __shared__ char dsm[];
    __shared__ uint32_t mask[128][4];
    uint32_t sbase = s2u(dsm);

    int bm = blockIdx.x, bn = blockIdx.y, b = blockIdx.z;
    int tid = threadIdx.x;
    int lane = tid & 31, warp = tid >> 5;
    int wy = warp & 1, wx = warp >> 1;      // 2 x 4 warp grid
    int wrow = wy * 64, wcol = wx * 32;
    int g = lane >> 2, tig = lane & 3;
    int n0 = bn * 128, m0 = bm * 128;
    const __nv_bfloat16* A  = g_kdb + (size_t)b*Nq*Cq;
    const __nv_bfloat16* Bt = g_d2b + (size_t)b*MPAD*Cq;

    int crow = tid >> 3, c16 = tid & 7;     // copy mapping (x4 rows per h)
    // prefetch stages 0..2 (chunks 0..2)
    #pragma unroll
    for (int kc = 0; kc < 3; kc++) {
        uint32_t aT = sbase + kc*2*TILEB;
        uint32_t bT = aT + TILEB;
        #pragma unroll
        for (int h = 0; h < 4; h++) {
            int row = crow + h*32;
            cpa16(aT + row*144 + c16*16, &A [(size_t)(n0 + row)*Cq + kc*64 + c16*8]);
            cpa16(bT + row*144 + c16*16, &Bt[(size_t)(m0 + row)*Cq + kc*64 + c16*8]);
        }
        asm volatile("cp.async.commit_group;" ::: "memory");
    }

    // penalty bitmask for this block's 128 rows x 128 local cols
    if (tid < 128) { mask[tid][0] = 0; mask[tid][1] = 0; mask[tid][2] = 0; mask[tid][3] = 0; }
    __syncthreads();
    {
        int row = tid >> 1;
        int qb  = (tid & 1) * 8;
        const int* nb = &g_nbr[(size_t)(b*Nq + n0 + row)*16];
        #pragma unroll
        for (int q = 0; q < 8; q++) {
            int loc = nb[qb + q] - m0;
            if (loc >= 0 && loc < 128)
                atomicOr(&mask[row][loc >> 5], 1u << (loc & 31));
        }
    }

    float c[4][4][4];
    #pragma unroll
    for (int mt = 0; mt < 4; mt++)
        #pragma unroll
        for (int nt = 0; nt < 4; nt++)
            #pragma unroll
            for (int r = 0; r < 4; r++) c[mt][nt][r] = 0.f;

    #pragma unroll
    for (int kc = 0; kc < 4; kc++) {
        // groups committed so far: 3 (+1 after kc=0 refill); need chunks 0..kc
        if (kc <= 1)      asm volatile("cp.async.wait_group 2;" ::: "memory");
        else if (kc == 2) asm volatile("cp.async.wait_group 1;" ::: "memory");
        else              asm volatile("cp.async.wait_group 0;" ::: "memory");
        __syncthreads();
        int buf = kc % 3;
        uint32_t aB = sbase + buf*2*TILEB;
        uint32_t bB = aB + TILEB;
        #pragma unroll
        for (int ks = 0; ks < 4; ks++) {
            int sk = ks * 16;
            uint32_t af[4][4], bf[4][2];
            #pragma unroll
            for (int mt = 0; mt < 4; mt++)
                ldsm_x4(af[mt], aB + (wrow + mt*16 + (lane & 15))*144
                                   + (sk + ((lane >> 4) << 3))*2);
            #pragma unroll
            for (int p = 0; p < 2; p++) {
                int mi = lane >> 3;
                int ntl = p*2 + (mi >> 1);
                int kh = mi & 1;
                uint32_t r[4];
                ldsm_x4(r, bB + (wcol + ntl*8 + (lane & 7))*144 + (sk + kh*8)*2);
                bf[p*2][0] = r[0]; bf[p*2][1] = r[1];
                bf[p*2+1][0] = r[2]; bf[p*2+1][1] = r[3];
            }
            #pragma unroll
            for (int mt = 0; mt < 4; mt++)
                #pragma unroll
                for (int nt = 0; nt < 4; nt++) {
                    asm volatile(
                        "mma.sync.aligned.m16n8k16.row.col.f32.bf16.bf16.f32 "
                        "{%0,%1,%2,%3}, {%4,%5,%6,%7}, {%8,%9}, {%0,%1,%2,%3};"
                        : "+f"(c[mt][nt][0]), "+f"(c[mt][nt][1]),
                          "+f"(c[mt][nt][2]), "+f"(c[mt][nt][3])
                        : "r"(af[mt][0]), "r"(af[mt][1]), "r"(af[mt][2]), "r"(af[mt][3]),
                          "r"(bf[nt][0]), "r"(bf[nt][1]));
                }
        }
        if (kc == 0) {      // only refill: chunk 3 into stage 0 (just consumed)
            __syncthreads();        // all warps done reading stage 0
            uint32_t aT = sbase;
            uint32_t bT = sbase + TILEB;
            #pragma unroll
            for (int h = 0; h < 4; h++) {
                int row = crow + h*32;
                cpa16(aT + row*144 + c16*16, &A [(size_t)(n0 + row)*Cq + 3*64 + c16*8]);
                cpa16(bT + row*144 + c16*16, &Bt[(size_t)(m0 + row)*Cq + 3*64 + c16*8]);
            }
            asm volatile("cp.async.commit_group;" ::: "memory");
        }
    }

    // ---- epilogue: per-thread running top-4 per row (sim = 2 - 2*acc) ----
    float t4[8][4];
    #pragma unroll
    for (int r = 0; r < 8; r++)
        #pragma unroll
        for (int s = 0; s < 4; s++) t4[r][s] = 1e30f;

    #pragma unroll
    for (int nt = 0; nt < 4; nt++) {
        int coll = wcol + nt*8 + tig*2;       // local col (even)
        int colg = m0 + coll;
        bool ok0 = colg < HWq, ok1 = (colg + 1) < HWq;
        #pragma unroll
        for (int mt = 0; mt < 4; mt++) {
            int lr0 = wrow + mt*16 + g;
            int lr1 = lr0 + 8;
            float v00 = 2.f - 2.f*c[mt][nt][0];
            float v01 = 2.f - 2.f*c[mt][nt][1];
            float v10 = 2.f - 2.f*c[mt][nt][2];
            float v11 = 2.f - 2.f*c[mt][nt][3];
            uint32_t m0b0 = mask[lr0][coll >> 5], m0b1 = mask[lr0][(coll+1) >> 5];
            uint32_t m1b0 = mask[lr1][coll >> 5], m1b1 = mask[lr1][(coll+1) >> 5];
            if (ok0 && !((m0b0 >> (coll & 31)) & 1))       ins4(t4[mt*2],     v00);
            if (ok1 && !((m0b1 >> ((coll+1) & 31)) & 1))   ins4(t4[mt*2],     v01);
            if (ok0 && !((m1b0 >> (coll & 31)) & 1))       ins4(t4[mt*2 + 1], v10);
            if (ok1 && !((m1b1 >> ((coll+1) & 31)) & 1))   ins4(t4[mt*2 + 1], v11);
        }
    }

    // ---- block reduction in reused dynamic smem: 64 cands -> top-4 per row --
    float* red = (float*)dsm;   // [128][64]
    __syncthreads();            // all ldsm reads of stage buffers done
    #pragma unroll
    for (int mt = 0; mt < 4; mt++) {
        int lr0 = wrow + mt*16 + g;
        int slot = (wx*4 + tig) * 4;
        *(float4*)&red[(lr0    )*64 + slot] = *(float4*)t4[mt*2];
        *(float4*)&red[(lr0 + 8)*64 + slot] = *(float4*)t4[mt*2 + 1];
    }
    __syncthreads();
    if (tid < 128) {
        float tt[4] = {1e30f, 1e30f, 1e30f, 1e30f};
        const float* r = &red[tid*64];
        #pragma unroll 8
        for (int q = 0; q < 64; q++) ins4(tt, r[q]);
        *(float4*)&g_part[((size_t)(b*Nq + n0 + tid)*NSPLIT + bm)*4] =
            make_float4(tt[0], tt[1], tt[2], tt[3]);
    }
}

// ---------------- K4: merge partials + hinge + fused final mean -------------
// one warp per row, 8 warps/block; per-block loss sum -> g_bsum; last
// finishing block sums the 512 block sums (deterministic fixed order).
__global__ __launch_bounds__(256) void k_merge(float* out) {
    __shared__ float wsum[8];
    __shared__ bool last;
    __shared__ float red[256];
    int wid = threadIdx.x >> 5;
    int row = blockIdx.x * 8 + wid;
    int lane = threadIdx.x & 31;
    const float4* p = (const float4*)&g_part[(size_t)row*NSPLIT*4];
    float t[4] = {1e30f, 1e30f, 1e30f, 1e30f};
    #pragma unroll 2
    for (int i = lane; i < NSPLIT; i += 32) {
        float4 v = p[i];
        if (v.x >= t[3]) continue;      // sorted quad can't contribute
        ins4(t, v.x); ins4(t, v.y); ins4(t, v.z); ins4(t, v.w);
    }
    #pragma unroll
    for (int off = 16; off > 0; off >>= 1) {
        float o0 = __shfl_xor_sync(0xffffffffu, t[0], off);
        float o1 = __shfl_xor_sync(0xffffffffu, t[1], off);
        float o2 = __shfl_xor_sync(0xffffffffu, t[2], off);
        float o3 = __shfl_xor_sync(0xffffffffu, t[3], off);
        float a[4] = {t[0], t[1], t[2], t[3]};
        float o[4] = {o0, o1, o2, o3};
        int ia = 0, ib = 0;
        #pragma unroll
        for (int k = 0; k < 4; k++) {
            float av = (ia < 4) ? a[ia] : 1e30f;
            float bv = (ib < 4) ? o[ib] : 1e30f;
            if (av <= bv) { t[k] = av; ia++; } else { t[k] = bv; ib++; }
        }
    }
    if (lane == 0) {
        float pos = g_pos[row];
        float lsum = 0.f;
        #pragma unroll
        for (int r = 0; r < 4; r++) lsum += fmaxf(pos - t[r] + 1.0f, 0.f);
        wsum[wid] = lsum;
    }
    __syncthreads();
    if (threadIdx.x == 0) {
        float bs = 0.f;
        #pragma unroll
        for (int j = 0; j < 8; j++) bs += wsum[j];
        g_bsum[blockIdx.x] = bs;
        __threadfence();
        last = (atomicAdd(&g_ctr, 1) == (int)gridDim.x - 1);
    }
    __syncthreads();
    if (last) {
        int tid = threadIdx.x;
        float acc = g_bsum[tid] + g_bsum[tid + 256];
        red[tid] = acc; __syncthreads();
        #pragma unroll
        for (int s = 128; s > 0; s >>= 1) {
            if (tid < s) red[tid] += red[tid + s];
            __syncthreads();
        }
        if (tid == 0) out[0] = red[0] / (float)(Bq*Nq*NUM_NEG);
    }
}

// ---------------- launch ----------------------------------------------------
extern "C" void kernel_launch(void* const* d_in, const int* in_sizes, int n_in,
                              void* d_out, int out_size) {
    const float* kp1      = (const float*)d_in[0];
    const float* w_kp1    = (const float*)d_in[1];
    const float* kp1_desc = (const float*)d_in[2];
    const float* desc2    = (const float*)d_in[3];
    const float* homo     = (const float*)d_in[4];
    float* out = (float*)d_out;

    cudaFuncSetAttribute(k_gemm_bf16, cudaFuncAttributeMaxDynamicSharedMemorySize, SMEM_GEMM);

    k_prep<<<dim3(MPAD/32, Bq), 256>>>(desc2);
    k_kd_pos<<<Bq*Nq/8, 256>>>(kp1_desc, w_kp1, kp1, homo);
    k_gemm_bf16<<<dim3(NSPLIT, Nq/128, Bq), 256, SMEM_GEMM>>>();
    k_merge<<<MERGEBLKS, 256>>>(out);
}